// round 2
// baseline (speedup 1.0000x reference)
#include <cuda_runtime.h>
#include <math.h>

// ---------------- problem constants ----------------
#define B_SZ 2
#define T_SZ 1024
#define D_SZ 1024
#define H_SZ 16
#define DH_SZ 64
#define FF_SZ 4096
#define L_SZ 2
#define V_SZ 32000
#define M_BLK 32
#define BS_SZ 32
#define TOPK 8
#define KEEP 128          // int(513 * 0.25)
#define EPSF 1e-6f
#define PI_D 3.14159265358979323846

// ---------------- scratch (device globals; no allocation allowed) ----------------
__device__ float d_x [B_SZ*T_SZ*D_SZ];
__device__ float d_h [B_SZ*T_SZ*D_SZ];
__device__ float d_q [B_SZ*T_SZ*D_SZ];
__device__ float d_k [B_SZ*T_SZ*D_SZ];
__device__ float d_v [B_SZ*T_SZ*D_SZ];
__device__ float d_o [B_SZ*T_SZ*D_SZ];
__device__ float d_sc[(size_t)B_SZ*H_SZ*T_SZ*T_SZ];   // 128 MB
__device__ float d_f1[B_SZ*T_SZ*FF_SZ];
__device__ float d_f3[B_SZ*T_SZ*FF_SZ];
__device__ float d_G [T_SZ*T_SZ];
__device__ float d_gk[T_SZ];
__device__ float d_rho[B_SZ*T_SZ];
__device__ int   d_sel[B_SZ*M_BLK];

// ---------------- generic tiled SGEMM: C[M,N] (+)= A[M,K] @ B[K,N] ----------------
// BM=128, BN=64, BK=16; 256 threads; 8x4 per-thread tile.
// Requires: M%128==0, N%64==0, K%16==0, lda/ldb/ldc %4==0 (true for all call sites).
// Two-level batch: z -> (zb = z/Hdim, zh = z%Hdim), offsets zb*s?b + zh*s?h.
#define BM 128
#define BN 64
#define BK 16

__global__ __launch_bounds__(256) void sgemm_kernel(
    const float* __restrict__ Ag, const float* __restrict__ Bg, float* __restrict__ Cg,
    int M, int N, int K, int lda, int ldb, int ldc,
    long sAb, long sBb, long sCb, long sAh, long sBh, long sCh, int Hdim, int beta)
{
    __shared__ float As[BK][BM + 4];   // padded stride 132 (16B aligned, reduces STS conflicts)
    __shared__ float Bs[BK][BN];

    int z  = blockIdx.z;
    int zb = z / Hdim, zh = z % Hdim;
    const float* A = Ag + zb * sAb + zh * sAh;
    const float* Bp = Bg + zb * sBb + zh * sBh;
    float* C = Cg + zb * sCb + zh * sCh;

    int tid = threadIdx.x;
    int tx = tid & 15, ty = tid >> 4;
    int row0 = blockIdx.y * BM;
    int col0 = blockIdx.x * BN;

    float acc[8][4];
#pragma unroll
    for (int i = 0; i < 8; i++)
#pragma unroll
        for (int j = 0; j < 4; j++) acc[i][j] = 0.f;

    int ar0 = tid >> 2;       // 0..63 (two rows per thread: +0, +64)
    int ac4 = tid & 3;        // which float4 along K
    int br  = tid >> 4;       // 0..15
    int bc4 = tid & 15;       // float4 along N

    for (int kt = 0; kt < K; kt += BK) {
#pragma unroll
        for (int i = 0; i < 2; i++) {
            int r = ar0 + i * 64;
            float4 va = *reinterpret_cast<const float4*>(
                A + (size_t)(row0 + r) * lda + kt + ac4 * 4);
            As[ac4 * 4 + 0][r] = va.x;
            As[ac4 * 4 + 1][r] = va.y;
            As[ac4 * 4 + 2][r] = va.z;
            As[ac4 * 4 + 3][r] = va.w;
        }
        {
            float4 vb = *reinterpret_cast<const float4*>(
                Bp + (size_t)(kt + br) * ldb + col0 + bc4 * 4);
            *reinterpret_cast<float4*>(&Bs[br][bc4 * 4]) = vb;
        }
        __syncthreads();

#pragma unroll
        for (int kk = 0; kk < BK; kk++) {
            float4 a0 = *reinterpret_cast<const float4*>(&As[kk][ty * 8]);
            float4 a1 = *reinterpret_cast<const float4*>(&As[kk][ty * 8 + 4]);
            float4 b0 = *reinterpret_cast<const float4*>(&Bs[kk][tx * 4]);
            float ra[8] = {a0.x, a0.y, a0.z, a0.w, a1.x, a1.y, a1.z, a1.w};
            float rb[4] = {b0.x, b0.y, b0.z, b0.w};
#pragma unroll
            for (int i = 0; i < 8; i++)
#pragma unroll
                for (int j = 0; j < 4; j++)
                    acc[i][j] = fmaf(ra[i], rb[j], acc[i][j]);
        }
        __syncthreads();
    }

#pragma unroll
    for (int i = 0; i < 8; i++) {
        size_t cidx = (size_t)(row0 + ty * 8 + i) * ldc + col0 + tx * 4;
        float4 outv;
        outv.x = acc[i][0]; outv.y = acc[i][1]; outv.z = acc[i][2]; outv.w = acc[i][3];
        if (beta) {
            float4 prev = *reinterpret_cast<const float4*>(C + cidx);
            outv.x += prev.x; outv.y += prev.y; outv.z += prev.z; outv.w += prev.w;
        }
        *reinterpret_cast<float4*>(C + cidx) = outv;
    }
}

// ---------------- embedding gather ----------------
__global__ void embed_kernel(const int* __restrict__ ids, const float* __restrict__ emb,
                             float* __restrict__ x)
{
    int idx = blockIdx.x * blockDim.x + threadIdx.x;   // B*T*D
    int d = idx & (D_SZ - 1);
    int bt = idx >> 10;
    x[idx] = emb[(size_t)ids[bt] * D_SZ + d];
}

// ---------------- Dirichlet low-pass kernel table ----------------
__global__ void dirichlet_kernel(float* __restrict__ g)
{
    int d = blockIdx.x * blockDim.x + threadIdx.x;     // 0..1023
    if (d >= T_SZ) return;
    double s = 0.0;
    for (int k = 1; k < KEEP; k++)
        s += cos(2.0 * PI_D * (double)k * (double)d / (double)T_SZ);
    g[d] = (float)((1.0 + 2.0 * s) / (double)T_SZ);
}

__global__ void buildG_kernel(const float* __restrict__ g, float* __restrict__ G)
{
    int i = blockIdx.x * blockDim.x + threadIdx.x;     // T*T
    int t = i >> 10, s = i & (T_SZ - 1);
    G[i] = g[(t - s) & (T_SZ - 1)];
}

// ---------------- rho = sum(hlp^2)/ (sum(x^2)+eps) per token ----------------
__global__ __launch_bounds__(256) void rho_kernel(const float* __restrict__ hlp,
                                                  const float* __restrict__ x,
                                                  float* __restrict__ rho)
{
    size_t row = (size_t)blockIdx.x * D_SZ;
    int tid = threadIdx.x;
    float s1 = 0.f, s2 = 0.f;
#pragma unroll
    for (int i = 0; i < 4; i++) {
        float a = hlp[row + tid + i * 256];
        float b = x  [row + tid + i * 256];
        s1 += a * a; s2 += b * b;
    }
    for (int o = 16; o > 0; o >>= 1) {
        s1 += __shfl_xor_sync(0xffffffffu, s1, o);
        s2 += __shfl_xor_sync(0xffffffffu, s2, o);
    }
    __shared__ float r1[8], r2[8];
    if ((tid & 31) == 0) { r1[tid >> 5] = s1; r2[tid >> 5] = s2; }
    __syncthreads();
    if (tid == 0) {
        float t1 = 0.f, t2 = 0.f;
        for (int i = 0; i < 8; i++) { t1 += r1[i]; t2 += r2[i]; }
        rho[blockIdx.x] = t1 / (t2 + EPSF);
    }
}

// ---------------- block quality + top-8 selection ----------------
__global__ void select_blocks(const float* __restrict__ rho, int* __restrict__ sel)
{
    __shared__ float bq[B_SZ][M_BLK];
    int tid = threadIdx.x;   // 64 threads
    if (tid < B_SZ * M_BLK) {
        int b = tid >> 5, m = tid & 31;
        float s = 0.f;
        for (int i = 0; i < BS_SZ; i++) s += rho[b * T_SZ + m * BS_SZ + i];
        bq[b][m] = s * (1.f / BS_SZ);
        sel[tid] = 0;
    }
    __syncthreads();
    if (tid < B_SZ) {
        int b = tid;
        bool picked[M_BLK];
        for (int m = 0; m < M_BLK; m++) picked[m] = false;
        for (int it = 0; it < TOPK; it++) {
            int best = -1; float bv = -3.4e38f;
            for (int m = 0; m < M_BLK; m++)
                if (!picked[m] && bq[b][m] > bv) { bv = bq[b][m]; best = m; }
            picked[best] = true;
            sel[b * M_BLK + best] = 1;
        }
    }
}

// ---------------- RMSNorm ----------------
__global__ __launch_bounds__(256) void rmsnorm_kernel(const float* __restrict__ x,
                                                      const float* __restrict__ w,
                                                      float* __restrict__ y)
{
    size_t row = (size_t)blockIdx.x * D_SZ;
    int tid = threadIdx.x;
    float v[4]; float s = 0.f;
#pragma unroll
    for (int i = 0; i < 4; i++) { v[i] = x[row + tid + i * 256]; s += v[i] * v[i]; }
    for (int o = 16; o > 0; o >>= 1) s += __shfl_xor_sync(0xffffffffu, s, o);
    __shared__ float red[8];
    if ((tid & 31) == 0) red[tid >> 5] = s;
    __syncthreads();
    float tot = 0.f;
    for (int i = 0; i < 8; i++) tot += red[i];
    float r = rsqrtf(tot * (1.f / D_SZ) + EPSF);
#pragma unroll
    for (int i = 0; i < 4; i++)
        y[row + tid + i * 256] = v[i] * r * w[tid + i * 256];
}

// ---------------- RoPE (in-place, q and k) ----------------
__global__ void rope_kernel(float* __restrict__ q, float* __restrict__ k)
{
    int idx = blockIdx.x * blockDim.x + threadIdx.x;   // B*T*H*32
    int j = idx & 31;
    int h = (idx >> 5) & (H_SZ - 1);
    int t = (idx >> 9) & (T_SZ - 1);
    int b = idx >> 19;
    float inv = (float)(1.0 / pow(10000.0, (double)(2 * j) / (double)DH_SZ));
    float fr = (float)t * inv;
    float c = cosf(fr), s = sinf(fr);
    size_t base = ((size_t)(b * T_SZ + t)) * D_SZ + h * DH_SZ + j;
    float q0 = q[base], q1 = q[base + 32];
    q[base]      = q0 * c - q1 * s;
    q[base + 32] = q1 * c + q0 * s;
    float k0 = k[base], k1 = k[base + 32];
    k[base]      = k0 * c - k1 * s;
    k[base + 32] = k1 * c + k0 * s;
}

// ---------------- masked attention scores: 64x64 tiles of Q K^T ----------------
__global__ __launch_bounds__(256) void attn_scores_kernel(
    const float* __restrict__ q, const float* __restrict__ k,
    const int* __restrict__ sel, float* __restrict__ scores)
{
    __shared__ float qs[64][65];
    __shared__ float ks[64][65];
    int bh = blockIdx.z;
    int b = bh / H_SZ, h = bh % H_SZ;
    int tq0 = blockIdx.y * 64, ts0 = blockIdx.x * 64;
    int tid = threadIdx.x;

#pragma unroll
    for (int i = 0; i < 16; i++) {
        int idx = tid + i * 256;
        int r = idx >> 6, c = idx & 63;
        qs[r][c] = q[(size_t)(b * T_SZ + tq0 + r) * D_SZ + h * DH_SZ + c];
        ks[r][c] = k[(size_t)(b * T_SZ + ts0 + r) * D_SZ + h * DH_SZ + c];
    }
    __syncthreads();

    int tx = tid & 15, ty = tid >> 4;
    float acc[4][4];
#pragma unroll
    for (int i = 0; i < 4; i++)
#pragma unroll
        for (int j = 0; j < 4; j++) acc[i][j] = 0.f;

    for (int kk = 0; kk < DH_SZ; kk++) {
        float a[4], bb[4];
#pragma unroll
        for (int i = 0; i < 4; i++) a[i] = qs[ty * 4 + i][kk];
#pragma unroll
        for (int j = 0; j < 4; j++) bb[j] = ks[tx * 4 + j][kk];
#pragma unroll
        for (int i = 0; i < 4; i++)
#pragma unroll
            for (int j = 0; j < 4; j++)
                acc[i][j] = fmaf(a[i], bb[j], acc[i][j]);
    }

    const float scale = 0.125f;   // 1/sqrt(64)
#pragma unroll
    for (int i = 0; i < 4; i++) {
        int tq = tq0 + ty * 4 + i;
#pragma unroll
        for (int j = 0; j < 4; j++) {
            int ts = ts0 + tx * 4 + j;
            bool allowed = (ts <= tq) &&
                           (sel[b * M_BLK + (ts >> 5)] || ((ts >> 5) == (tq >> 5)));
            scores[((size_t)bh * T_SZ + tq) * T_SZ + ts] =
                acc[i][j] * scale + (allowed ? 0.f : -1e9f);
        }
    }
}

// ---------------- row softmax over T ----------------
__global__ __launch_bounds__(256) void softmax_kernel(float* __restrict__ s)
{
    size_t row = (size_t)blockIdx.x * T_SZ;
    int tid = threadIdx.x;
    float v[4];
    float mx = -3.4e38f;
#pragma unroll
    for (int i = 0; i < 4; i++) { v[i] = s[row + tid + i * 256]; mx = fmaxf(mx, v[i]); }
    for (int o = 16; o > 0; o >>= 1) mx = fmaxf(mx, __shfl_xor_sync(0xffffffffu, mx, o));
    __shared__ float red[8];
    if ((tid & 31) == 0) red[tid >> 5] = mx;
    __syncthreads();
    float m = red[0];
    for (int i = 1; i < 8; i++) m = fmaxf(m, red[i]);
    __syncthreads();
    float sum = 0.f;
#pragma unroll
    for (int i = 0; i < 4; i++) { v[i] = expf(v[i] - m); sum += v[i]; }
    for (int o = 16; o > 0; o >>= 1) sum += __shfl_xor_sync(0xffffffffu, sum, o);
    if ((tid & 31) == 0) red[tid >> 5] = sum;
    __syncthreads();
    float tot = 0.f;
    for (int i = 0; i < 8; i++) tot += red[i];
    float inv = 1.f / tot;
#pragma unroll
    for (int i = 0; i < 4; i++) s[row + tid + i * 256] = v[i] * inv;
}

// ---------------- SiLU gate: f1 = silu(f1) * f3 ----------------
__global__ void silu_mul_kernel(float* __restrict__ f1, const float* __restrict__ f3)
{
    int idx = blockIdx.x * blockDim.x + threadIdx.x;
    float a = f1[idx];
    f1[idx] = a / (1.f + expf(-a)) * f3[idx];
}

// ---------------- host-side launcher ----------------
static void gemm(const float* A, const float* Bp, float* C,
                 int M, int N, int K, int lda, int ldb, int ldc,
                 long sAb, long sBb, long sCb, long sAh, long sBh, long sCh,
                 int Hdim, int nbatch, int beta)
{
    dim3 grid(N / BN, M / BM, nbatch);
    sgemm_kernel<<<grid, 256>>>(A, Bp, C, M, N, K, lda, ldb, ldc,
                                sAb, sBb, sCb, sAh, sBh, sCh, Hdim, beta);
}

extern "C" void kernel_launch(void* const* d_in, const int* in_sizes, int n_in,
                              void* d_out, int out_size)
{
    const int*   ids        = (const int*)  d_in[0];
    const float* emb        = (const float*)d_in[1];
    const float* wq         = (const float*)d_in[2];
    const float* wk         = (const float*)d_in[3];
    const float* wv         = (const float*)d_in[4];
    const float* wo         = (const float*)d_in[5];
    const float* w1         = (const float*)d_in[6];
    const float* w2         = (const float*)d_in[7];
    const float* w3         = (const float*)d_in[8];
    const float* attn_norm  = (const float*)d_in[9];
    const float* ffn_norm   = (const float*)d_in[10];
    const float* final_norm = (const float*)d_in[11];
    const float* lm_head    = (const float*)d_in[12];
    float* out = (float*)d_out;

    float *x, *h, *q, *k, *v, *o, *sc, *f1, *f3, *G, *gk, *rho;
    int* sel;
    cudaGetSymbolAddress((void**)&x,   d_x);
    cudaGetSymbolAddress((void**)&h,   d_h);
    cudaGetSymbolAddress((void**)&q,   d_q);
    cudaGetSymbolAddress((void**)&k,   d_k);
    cudaGetSymbolAddress((void**)&v,   d_v);
    cudaGetSymbolAddress((void**)&o,   d_o);
    cudaGetSymbolAddress((void**)&sc,  d_sc);
    cudaGetSymbolAddress((void**)&f1,  d_f1);
    cudaGetSymbolAddress((void**)&f3,  d_f3);
    cudaGetSymbolAddress((void**)&G,   d_G);
    cudaGetSymbolAddress((void**)&gk,  d_gk);
    cudaGetSymbolAddress((void**)&rho, d_rho);
    cudaGetSymbolAddress((void**)&sel, d_sel);

    const int BT = B_SZ * T_SZ;            // 2048
    const long DD = (long)D_SZ * D_SZ;

    // 1) embedding
    embed_kernel<<<(B_SZ * T_SZ * D_SZ) / 256, 256>>>(ids, emb, x);

    // 2) low-pass quality score -> block selection
    dirichlet_kernel<<<T_SZ / 256, 256>>>(gk);
    buildG_kernel<<<(T_SZ * T_SZ) / 256, 256>>>(gk, G);
    // hlp (into h): per-batch  h[b] = G @ x[b]
    gemm(G, x, h, T_SZ, D_SZ, T_SZ, T_SZ, D_SZ, D_SZ,
         0, (long)T_SZ * D_SZ, (long)T_SZ * D_SZ, 0, 0, 0, 1, B_SZ, 0);
    rho_kernel<<<BT, 256>>>(h, x, rho);
    select_blocks<<<1, 64>>>(rho, sel);

    // 3) transformer layers
    for (int l = 0; l < L_SZ; l++) {
        rmsnorm_kernel<<<BT, 256>>>(x, attn_norm + (size_t)l * D_SZ, h);

        gemm(h, wq + l * DD, q, BT, D_SZ, D_SZ, D_SZ, D_SZ, D_SZ,
             0, 0, 0, 0, 0, 0, 1, 1, 0);
        gemm(h, wk + l * DD, k, BT, D_SZ, D_SZ, D_SZ, D_SZ, D_SZ,
             0, 0, 0, 0, 0, 0, 1, 1, 0);
        gemm(h, wv + l * DD, v, BT, D_SZ, D_SZ, D_SZ, D_SZ, D_SZ,
             0, 0, 0, 0, 0, 0, 1, 1, 0);

        rope_kernel<<<(B_SZ * T_SZ * H_SZ * 32) / 256, 256>>>(q, k);

        attn_scores_kernel<<<dim3(T_SZ / 64, T_SZ / 64, B_SZ * H_SZ), 256>>>(q, k, sel, sc);
        softmax_kernel<<<B_SZ * H_SZ * T_SZ, 256>>>(sc);

        // o[b,:,h*64:(h+1)*64] = attn[b,h] @ v[b,:,h*64:(h+1)*64]
        gemm(sc, v, o, T_SZ, DH_SZ, T_SZ, T_SZ, D_SZ, D_SZ,
             (long)H_SZ * T_SZ * T_SZ, (long)T_SZ * D_SZ, (long)T_SZ * D_SZ,
             (long)T_SZ * T_SZ, DH_SZ, DH_SZ, H_SZ, B_SZ * H_SZ, 0);

        // x += o @ wo[l]
        gemm(o, wo + l * DD, x, BT, D_SZ, D_SZ, D_SZ, D_SZ, D_SZ,
             0, 0, 0, 0, 0, 0, 1, 1, 1);

        // FFN
        rmsnorm_kernel<<<BT, 256>>>(x, ffn_norm + (size_t)l * D_SZ, h);
        gemm(h, w1 + (size_t)l * D_SZ * FF_SZ, f1, BT, FF_SZ, D_SZ, D_SZ, FF_SZ, FF_SZ,
             0, 0, 0, 0, 0, 0, 1, 1, 0);
        gemm(h, w3 + (size_t)l * D_SZ * FF_SZ, f3, BT, FF_SZ, D_SZ, D_SZ, FF_SZ, FF_SZ,
             0, 0, 0, 0, 0, 0, 1, 1, 0);
        silu_mul_kernel<<<(BT * FF_SZ) / 256, 256>>>(f1, f3);
        gemm(f1, w2 + (size_t)l * FF_SZ * D_SZ, x, BT, D_SZ, FF_SZ, FF_SZ, D_SZ, D_SZ,
             0, 0, 0, 0, 0, 0, 1, 1, 1);
    }

    // 4) final norm + lm_head
    rmsnorm_kernel<<<BT, 256>>>(x, final_norm, h);
    gemm(h, lm_head, out, BT, V_SZ, D_SZ, D_SZ, V_SZ, V_SZ,
         0, 0, 0, 0, 0, 0, 1, 1, 0);
}

// round 4
// speedup vs baseline: 1.4789x; 1.4789x over previous
#include <cuda_runtime.h>
#include <math.h>

// ---------------- problem constants ----------------
#define B_SZ 2
#define T_SZ 1024
#define D_SZ 1024
#define H_SZ 16
#define DH_SZ 64
#define FF_SZ 4096
#define L_SZ 2
#define V_SZ 32000
#define M_BLK 32
#define BS_SZ 32
#define TOPK 8
#define KEEP 128          // int(513 * 0.25)
#define EPSF 1e-6f
#define PI_D 3.14159265358979323846

// ---------------- scratch (device globals; no allocation allowed) ----------------
__device__ float d_x [B_SZ*T_SZ*D_SZ];
__device__ float d_h [B_SZ*T_SZ*D_SZ];
__device__ float d_q [B_SZ*T_SZ*D_SZ];
__device__ float d_k [B_SZ*T_SZ*D_SZ];
__device__ float d_v [B_SZ*T_SZ*D_SZ];
__device__ float d_o [B_SZ*T_SZ*D_SZ];
__device__ float d_kt[B_SZ*T_SZ*D_SZ];                 // k transposed per (b,h): [B,H,DH,T]
__device__ float d_sc[(size_t)B_SZ*H_SZ*T_SZ*T_SZ];   // 128 MB
__device__ float d_f1[B_SZ*T_SZ*FF_SZ];
__device__ float d_f3[B_SZ*T_SZ*FF_SZ];
__device__ float d_G [T_SZ*T_SZ];
__device__ float d_gk[T_SZ];
__device__ float d_rho[B_SZ*T_SZ];
__device__ int   d_sel[B_SZ*M_BLK];

// ---------------- split fp32 -> (hi, lo) bf16x2 pair ----------------
// packed bf16x2: low 16 bits = v0, high 16 bits = v1.
__device__ __forceinline__ void split2(float v0, float v1, unsigned &hi, unsigned &lo)
{
    asm("cvt.rn.bf16x2.f32 %0, %1, %2;" : "=r"(hi) : "f"(v1), "f"(v0));
    float h0 = __int_as_float(hi << 16);
    float h1 = __int_as_float(hi & 0xffff0000u);
    asm("cvt.rn.bf16x2.f32 %0, %1, %2;" : "=r"(lo) : "f"(v1 - h1), "f"(v0 - h0));
}

#define MMA_BF16(ACC, A0, A1, A2, A3, B0, B1)                                    \
    asm volatile(                                                                \
        "mma.sync.aligned.m16n8k16.row.col.f32.bf16.bf16.f32 "                   \
        "{%0,%1,%2,%3}, {%4,%5,%6,%7}, {%8,%9}, {%0,%1,%2,%3};"                  \
        : "+f"(ACC[0]), "+f"(ACC[1]), "+f"(ACC[2]), "+f"(ACC[3])                 \
        : "r"(A0), "r"(A1), "r"(A2), "r"(A3), "r"(B0), "r"(B1))

// =====================================================================
// split-bf16 (3xMMA) tensor-core GEMM: C[M,N] (+)= A[M,K] @ B[K,N]
// fp32 in/out, effective ~18-bit mantissa precision.
// BM=128, BK=16, BN in {128,64}; 256 threads = 8 warps.
// A tile in smem as [m][k] (stride 20), B tile as [k][n] (stride BN+8).
// cp.async double-buffered.
// Requires M%128==0, N%BN==0, K%16==0, 16B-aligned rows.
// Two-level batch: z -> (zb=z/Hdim, zh=z%Hdim).
// =====================================================================
template<int BN, int WM, int WN>
__global__ __launch_bounds__(256, 1) void mma_gemm_kernel(
    const float* __restrict__ Ag, const float* __restrict__ Bg, float* __restrict__ Cg,
    int K, int lda, int ldb, int ldc,
    long sAb, long sBb, long sCb, long sAh, long sBh, long sCh, int Hdim, int beta)
{
    constexpr int BM = 128, BK = 16;
    constexpr int AM = BM / WM / 16;   // m16 atoms per warp
    constexpr int AN = BN / WN / 8;    // n8 atoms per warp
    constexpr int LDA_S = BK + 4;      // 20 floats
    constexpr int LDB_S = BN + 8;

    __shared__ float As[2][BM][LDA_S];
    __shared__ float Bs[2][BK][LDB_S];

    int z  = blockIdx.z;
    int zb = z / Hdim, zh = z % Hdim;
    const float* A  = Ag + zb * sAb + zh * sAh;
    const float* Bp = Bg + zb * sBb + zh * sBh;
    float*       C  = Cg + zb * sCb + zh * sCh;

    const int tid  = threadIdx.x;
    const int row0 = blockIdx.y * BM;
    const int col0 = blockIdx.x * BN;
    const int lane = tid & 31;
    const int w    = tid >> 5;
    const int wm   = w % WM, wn = w / WM;
    const int mW   = wm * (BM / WM);
    const int nW   = wn * (BN / WN);

    float acc[AM][AN][4];
#pragma unroll
    for (int i = 0; i < AM; i++)
#pragma unroll
        for (int j = 0; j < AN; j++)
#pragma unroll
            for (int r = 0; r < 4; r++) acc[i][j][r] = 0.f;

    auto load_tile = [&](int s, int kt) {
        // A: BM x BK floats = 512 16B-chunks
#pragma unroll
        for (int i = 0; i < (BM * BK / 4) / 256; i++) {
            int ch = tid + i * 256;
            int r = ch >> 2, c4 = ch & 3;
            unsigned dst = (unsigned)__cvta_generic_to_shared(&As[s][r][c4 * 4]);
            const float* src = A + (size_t)(row0 + r) * lda + kt + c4 * 4;
            asm volatile("cp.async.cg.shared.global [%0], [%1], 16;\n" :: "r"(dst), "l"(src));
        }
        // B: BK x BN floats
        constexpr int BCH = BK * BN / 4;
#pragma unroll
        for (int i = 0; i < BCH / 256; i++) {
            int ch = tid + i * 256;
            int r = ch / (BN / 4), c4 = ch % (BN / 4);
            unsigned dst = (unsigned)__cvta_generic_to_shared(&Bs[s][r][c4 * 4]);
            const float* src = Bp + (size_t)(kt + r) * ldb + col0 + c4 * 4;
            asm volatile("cp.async.cg.shared.global [%0], [%1], 16;\n" :: "r"(dst), "l"(src));
        }
    };

    load_tile(0, 0);
    asm volatile("cp.async.commit_group;\n" ::: "memory");

    const int ntiles = K / BK;
    for (int t = 0; t < ntiles; t++) {
        int s = t & 1;
        if (t + 1 < ntiles) {
            load_tile(s ^ 1, (t + 1) * BK);
            asm volatile("cp.async.commit_group;\n" ::: "memory");
            asm volatile("cp.async.wait_group 1;\n" ::: "memory");
        } else {
            asm volatile("cp.async.wait_group 0;\n" ::: "memory");
        }
        __syncthreads();

        // ---- fragment load + split (one k16 chunk per tile) ----
        unsigned ahi[AM][4], alo[AM][4], bhi[AN][2], blo[AN][2];
        const int c0 = (lane & 3) * 2;
#pragma unroll
        for (int am = 0; am < AM; am++) {
            int r = mW + am * 16 + (lane >> 2);
            float2 v00 = *reinterpret_cast<const float2*>(&As[s][r    ][c0]);
            float2 v10 = *reinterpret_cast<const float2*>(&As[s][r + 8][c0]);
            float2 v01 = *reinterpret_cast<const float2*>(&As[s][r    ][c0 + 8]);
            float2 v11 = *reinterpret_cast<const float2*>(&As[s][r + 8][c0 + 8]);
            split2(v00.x, v00.y, ahi[am][0], alo[am][0]);
            split2(v10.x, v10.y, ahi[am][1], alo[am][1]);
            split2(v01.x, v01.y, ahi[am][2], alo[am][2]);
            split2(v11.x, v11.y, ahi[am][3], alo[am][3]);
        }
#pragma unroll
        for (int an = 0; an < AN; an++) {
            int c = nW + an * 8 + (lane >> 2);
            split2(Bs[s][c0    ][c], Bs[s][c0 + 1][c], bhi[an][0], blo[an][0]);
            split2(Bs[s][c0 + 8][c], Bs[s][c0 + 9][c], bhi[an][1], blo[an][1]);
        }

        // ---- 3-pass MMA: hi*hi + hi*lo + lo*hi ----
#pragma unroll
        for (int am = 0; am < AM; am++)
#pragma unroll
            for (int an = 0; an < AN; an++) {
                MMA_BF16(acc[am][an], ahi[am][0], ahi[am][1], ahi[am][2], ahi[am][3],
                         bhi[an][0], bhi[an][1]);
                MMA_BF16(acc[am][an], ahi[am][0], ahi[am][1], ahi[am][2], ahi[am][3],
                         blo[an][0], blo[an][1]);
                MMA_BF16(acc[am][an], alo[am][0], alo[am][1], alo[am][2], alo[am][3],
                         bhi[an][0], bhi[an][1]);
            }
        __syncthreads();
    }

    // epilogue
#pragma unroll
    for (int am = 0; am < AM; am++)
#pragma unroll
        for (int an = 0; an < AN; an++) {
            int r = row0 + mW + am * 16 + (lane >> 2);
            int c = col0 + nW + an * 8 + (lane & 3) * 2;
            size_t i0 = (size_t)r * ldc + c;
            size_t i1 = (size_t)(r + 8) * ldc + c;
            float2 v0 = make_float2(acc[am][an][0], acc[am][an][1]);
            float2 v1 = make_float2(acc[am][an][2], acc[am][an][3]);
            if (beta) {
                float2 p0 = *reinterpret_cast<const float2*>(C + i0);
                float2 p1 = *reinterpret_cast<const float2*>(C + i1);
                v0.x += p0.x; v0.y += p0.y; v1.x += p1.x; v1.y += p1.y;
            }
            *reinterpret_cast<float2*>(C + i0) = v0;
            *reinterpret_cast<float2*>(C + i1) = v1;
        }
}

// ---------------- embedding gather ----------------
__global__ void embed_kernel(const int* __restrict__ ids, const float* __restrict__ emb,
                             float* __restrict__ x)
{
    int idx = blockIdx.x * blockDim.x + threadIdx.x;   // B*T*D
    int d = idx & (D_SZ - 1);
    int bt = idx >> 10;
    x[idx] = emb[(size_t)ids[bt] * D_SZ + d];
}

// ---------------- Dirichlet low-pass kernel table ----------------
__global__ void dirichlet_kernel(float* __restrict__ g)
{
    int d = blockIdx.x * blockDim.x + threadIdx.x;     // 0..1023
    if (d >= T_SZ) return;
    double s = 0.0;
    for (int k = 1; k < KEEP; k++)
        s += cos(2.0 * PI_D * (double)k * (double)d / (double)T_SZ);
    g[d] = (float)((1.0 + 2.0 * s) / (double)T_SZ);
}

__global__ void buildG_kernel(const float* __restrict__ g, float* __restrict__ G)
{
    int i = blockIdx.x * blockDim.x + threadIdx.x;     // T*T
    int t = i >> 10, s = i & (T_SZ - 1);
    G[i] = g[(t - s) & (T_SZ - 1)];
}

// ---------------- rho = sum(hlp^2)/(sum(x^2)+eps) per token ----------------
__global__ __launch_bounds__(256) void rho_kernel(const float* __restrict__ hlp,
                                                  const float* __restrict__ x,
                                                  float* __restrict__ rho)
{
    size_t row = (size_t)blockIdx.x * D_SZ;
    int tid = threadIdx.x;
    float s1 = 0.f, s2 = 0.f;
#pragma unroll
    for (int i = 0; i < 4; i++) {
        float a = hlp[row + tid + i * 256];
        float b = x  [row + tid + i * 256];
        s1 += a * a; s2 += b * b;
    }
    for (int o = 16; o > 0; o >>= 1) {
        s1 += __shfl_xor_sync(0xffffffffu, s1, o);
        s2 += __shfl_xor_sync(0xffffffffu, s2, o);
    }
    __shared__ float r1[8], r2[8];
    if ((tid & 31) == 0) { r1[tid >> 5] = s1; r2[tid >> 5] = s2; }
    __syncthreads();
    if (tid == 0) {
        float t1 = 0.f, t2 = 0.f;
        for (int i = 0; i < 8; i++) { t1 += r1[i]; t2 += r2[i]; }
        rho[blockIdx.x] = t1 / (t2 + EPSF);
    }
}

// ---------------- block quality + top-8 selection ----------------
__global__ void select_blocks(const float* __restrict__ rho, int* __restrict__ sel)
{
    __shared__ float bq[B_SZ][M_BLK];
    int tid = threadIdx.x;   // 64 threads
    if (tid < B_SZ * M_BLK) {
        int b = tid >> 5, m = tid & 31;
        float s = 0.f;
        for (int i = 0; i < BS_SZ; i++) s += rho[b * T_SZ + m * BS_SZ + i];
        bq[b][m] = s * (1.f / BS_SZ);
        sel[tid] = 0;
    }
    __syncthreads();
    if (tid < B_SZ) {
        int b = tid;
        bool picked[M_BLK];
        for (int m = 0; m < M_BLK; m++) picked[m] = false;
        for (int it = 0; it < TOPK; it++) {
            int best = -1; float bv = -3.4e38f;
            for (int m = 0; m < M_BLK; m++)
                if (!picked[m] && bq[b][m] > bv) { bv = bq[b][m]; best = m; }
            picked[best] = true;
            sel[b * M_BLK + best] = 1;
        }
    }
}

// ---------------- RMSNorm ----------------
__global__ __launch_bounds__(256) void rmsnorm_kernel(const float* __restrict__ x,
                                                      const float* __restrict__ w,
                                                      float* __restrict__ y)
{
    size_t row = (size_t)blockIdx.x * D_SZ;
    int tid = threadIdx.x;
    float v[4]; float s = 0.f;
#pragma unroll
    for (int i = 0; i < 4; i++) { v[i] = x[row + tid + i * 256]; s += v[i] * v[i]; }
    for (int o = 16; o > 0; o >>= 1) s += __shfl_xor_sync(0xffffffffu, s, o);
    __shared__ float red[8];
    if ((tid & 31) == 0) red[tid >> 5] = s;
    __syncthreads();
    float tot = 0.f;
    for (int i = 0; i < 8; i++) tot += red[i];
    float r = rsqrtf(tot * (1.f / D_SZ) + EPSF);
#pragma unroll
    for (int i = 0; i < 4; i++)
        y[row + tid + i * 256] = v[i] * r * w[tid + i * 256];
}

// ---------------- RoPE (in-place, q and k) ----------------
__global__ void rope_kernel(float* __restrict__ q, float* __restrict__ k)
{
    int idx = blockIdx.x * blockDim.x + threadIdx.x;   // B*T*H*32
    int j = idx & 31;
    int h = (idx >> 5) & (H_SZ - 1);
    int t = (idx >> 9) & (T_SZ - 1);
    int b = idx >> 19;
    float inv = (float)(1.0 / pow(10000.0, (double)(2 * j) / (double)DH_SZ));
    float fr = (float)t * inv;
    float c = cosf(fr), s = sinf(fr);
    size_t base = ((size_t)(b * T_SZ + t)) * D_SZ + h * DH_SZ + j;
    float q0 = q[base], q1 = q[base + 32];
    q[base]      = q0 * c - q1 * s;
    q[base + 32] = q1 * c + q0 * s;
    float k0 = k[base], k1 = k[base + 32];
    k[base]      = k0 * c - k1 * s;
    k[base + 32] = k1 * c + k0 * s;
}

// ---------------- K transpose: kT[b,h,dh,t] = k[b,t,h*64+dh] ----------------
__global__ void ktrans_kernel(const float* __restrict__ k, float* __restrict__ kt)
{
    int idx = blockIdx.x * blockDim.x + threadIdx.x;   // B*H*DH*T
    int t  = idx & (T_SZ - 1);
    int dh = (idx >> 10) & (DH_SZ - 1);
    int h  = (idx >> 16) & (H_SZ - 1);
    int b  = idx >> 20;
    kt[idx] = k[(size_t)(b * T_SZ + t) * D_SZ + h * DH_SZ + dh];
}

// ---------------- masked softmax over T (scale+mask fused) ----------------
__global__ __launch_bounds__(256) void masked_softmax_kernel(float* __restrict__ s,
                                                             const int* __restrict__ sel)
{
    int gid = blockIdx.x;                 // bh*T + tq
    int tq = gid & (T_SZ - 1);
    int b  = gid / (H_SZ * T_SZ);
    size_t row = (size_t)gid * T_SZ;
    int tid = threadIdx.x;
    const float scale = 0.125f;           // 1/sqrt(64)
    int qblk = tq >> 5;

    float v[4];
    float mx = -3.4e38f;
#pragma unroll
    for (int i = 0; i < 4; i++) {
        int ts = tid + i * 256;
        bool allowed = (ts <= tq) &&
                       (sel[b * M_BLK + (ts >> 5)] || ((ts >> 5) == qblk));
        v[i] = s[row + ts] * scale + (allowed ? 0.f : -1e9f);
        mx = fmaxf(mx, v[i]);
    }
    for (int o = 16; o > 0; o >>= 1) mx = fmaxf(mx, __shfl_xor_sync(0xffffffffu, mx, o));
    __shared__ float red[8];
    if ((tid & 31) == 0) red[tid >> 5] = mx;
    __syncthreads();
    float m = red[0];
    for (int i = 1; i < 8; i++) m = fmaxf(m, red[i]);
    __syncthreads();
    float sum = 0.f;
#pragma unroll
    for (int i = 0; i < 4; i++) { v[i] = expf(v[i] - m); sum += v[i]; }
    for (int o = 16; o > 0; o >>= 1) sum += __shfl_xor_sync(0xffffffffu, sum, o);
    if ((tid & 31) == 0) red[tid >> 5] = sum;
    __syncthreads();
    float tot = 0.f;
    for (int i = 0; i < 8; i++) tot += red[i];
    float inv = 1.f / tot;
#pragma unroll
    for (int i = 0; i < 4; i++) s[row + tid + i * 256] = v[i] * inv;
}

// ---------------- SiLU gate: f1 = silu(f1) * f3 ----------------
__global__ void silu_mul_kernel(float* __restrict__ f1, const float* __restrict__ f3)
{
    int idx = blockIdx.x * blockDim.x + threadIdx.x;
    float a = f1[idx];
    f1[idx] = a / (1.f + expf(-a)) * f3[idx];
}

// ---------------- host-side launcher ----------------
static void gemm(const float* A, const float* Bp, float* C,
                 int M, int N, int K, int lda, int ldb, int ldc,
                 long sAb, long sBb, long sCb, long sAh, long sBh, long sCh,
                 int Hdim, int nbatch, int beta)
{
    if (N % 128 == 0) {
        dim3 grid(N / 128, M / 128, nbatch);
        mma_gemm_kernel<128, 2, 4><<<grid, 256>>>(A, Bp, C, K, lda, ldb, ldc,
                                                  sAb, sBb, sCb, sAh, sBh, sCh, Hdim, beta);
    } else {
        dim3 grid(N / 64, M / 128, nbatch);
        mma_gemm_kernel<64, 4, 2><<<grid, 256>>>(A, Bp, C, K, lda, ldb, ldc,
                                                 sAb, sBb, sCb, sAh, sBh, sCh, Hdim, beta);
    }
}

extern "C" void kernel_launch(void* const* d_in, const int* in_sizes, int n_in,
                              void* d_out, int out_size)
{
    const int*   ids        = (const int*)  d_in[0];
    const float* emb        = (const float*)d_in[1];
    const float* wq         = (const float*)d_in[2];
    const float* wk         = (const float*)d_in[3];
    const float* wv         = (const float*)d_in[4];
    const float* wo         = (const float*)d_in[5];
    const float* w1         = (const float*)d_in[6];
    const float* w2         = (const float*)d_in[7];
    const float* w3         = (const float*)d_in[8];
    const float* attn_norm  = (const float*)d_in[9];
    const float* ffn_norm   = (const float*)d_in[10];
    const float* final_norm = (const float*)d_in[11];
    const float* lm_head    = (const float*)d_in[12];
    float* out = (float*)d_out;

    float *x, *h, *q, *k, *v, *o, *kt, *sc, *f1, *f3, *G, *gk, *rho;
    int* sel;
    cudaGetSymbolAddress((void**)&x,   d_x);
    cudaGetSymbolAddress((void**)&h,   d_h);
    cudaGetSymbolAddress((void**)&q,   d_q);
    cudaGetSymbolAddress((void**)&k,   d_k);
    cudaGetSymbolAddress((void**)&v,   d_v);
    cudaGetSymbolAddress((void**)&o,   d_o);
    cudaGetSymbolAddress((void**)&kt,  d_kt);
    cudaGetSymbolAddress((void**)&sc,  d_sc);
    cudaGetSymbolAddress((void**)&f1,  d_f1);
    cudaGetSymbolAddress((void**)&f3,  d_f3);
    cudaGetSymbolAddress((void**)&G,   d_G);
    cudaGetSymbolAddress((void**)&gk,  d_gk);
    cudaGetSymbolAddress((void**)&rho, d_rho);
    cudaGetSymbolAddress((void**)&sel, d_sel);

    const int BT = B_SZ * T_SZ;            // 2048
    const long DD = (long)D_SZ * D_SZ;

    // 1) embedding
    embed_kernel<<<(B_SZ * T_SZ * D_SZ) / 256, 256>>>(ids, emb, x);

    // 2) low-pass quality score -> block selection
    dirichlet_kernel<<<T_SZ / 256, 256>>>(gk);
    buildG_kernel<<<(T_SZ * T_SZ) / 256, 256>>>(gk, G);
    gemm(G, x, h, T_SZ, D_SZ, T_SZ, T_SZ, D_SZ, D_SZ,
         0, (long)T_SZ * D_SZ, (long)T_SZ * D_SZ, 0, 0, 0, 1, B_SZ, 0);
    rho_kernel<<<BT, 256>>>(h, x, rho);
    select_blocks<<<1, 64>>>(rho, sel);

    // 3) transformer layers
    for (int l = 0; l < L_SZ; l++) {
        rmsnorm_kernel<<<BT, 256>>>(x, attn_norm + (size_t)l * D_SZ, h);

        gemm(h, wq + l * DD, q, BT, D_SZ, D_SZ, D_SZ, D_SZ, D_SZ,
             0, 0, 0, 0, 0, 0, 1, 1, 0);
        gemm(h, wk + l * DD, k, BT, D_SZ, D_SZ, D_SZ, D_SZ, D_SZ,
             0, 0, 0, 0, 0, 0, 1, 1, 0);
        gemm(h, wv + l * DD, v, BT, D_SZ, D_SZ, D_SZ, D_SZ, D_SZ,
             0, 0, 0, 0, 0, 0, 1, 1, 0);

        rope_kernel<<<(B_SZ * T_SZ * H_SZ * 32) / 256, 256>>>(q, k);
        ktrans_kernel<<<(B_SZ * T_SZ * D_SZ) / 256, 256>>>(k, kt);

        // scores[b,h] = q[b,:,h] @ kT[b,h]    (M=T, N=T, K=DH)
        gemm(q, kt, sc, T_SZ, T_SZ, DH_SZ, D_SZ, T_SZ, T_SZ,
             (long)T_SZ * D_SZ, (long)H_SZ * DH_SZ * T_SZ, (long)H_SZ * T_SZ * T_SZ,
             DH_SZ, (long)DH_SZ * T_SZ, (long)T_SZ * T_SZ, H_SZ, B_SZ * H_SZ, 0);

        masked_softmax_kernel<<<B_SZ * H_SZ * T_SZ, 256>>>(sc, sel);

        // o[b,:,h*64:(h+1)*64] = attn[b,h] @ v[b,:,h*64:(h+1)*64]
        gemm(sc, v, o, T_SZ, DH_SZ, T_SZ, T_SZ, D_SZ, D_SZ,
             (long)H_SZ * T_SZ * T_SZ, (long)T_SZ * D_SZ, (long)T_SZ * D_SZ,
             (long)T_SZ * T_SZ, DH_SZ, DH_SZ, H_SZ, B_SZ * H_SZ, 0);

        // x += o @ wo[l]
        gemm(o, wo + l * DD, x, BT, D_SZ, D_SZ, D_SZ, D_SZ, D_SZ,
             0, 0, 0, 0, 0, 0, 1, 1, 1);

        // FFN
        rmsnorm_kernel<<<BT, 256>>>(x, ffn_norm + (size_t)l * D_SZ, h);
        gemm(h, w1 + (size_t)l * D_SZ * FF_SZ, f1, BT, FF_SZ, D_SZ, D_SZ, FF_SZ, FF_SZ,
             0, 0, 0, 0, 0, 0, 1, 1, 0);
        gemm(h, w3 + (size_t)l * D_SZ * FF_SZ, f3, BT, FF_SZ, D_SZ, D_SZ, FF_SZ, FF_SZ,
             0, 0, 0, 0, 0, 0, 1, 1, 0);
        silu_mul_kernel<<<(BT * FF_SZ) / 256, 256>>>(f1, f3);
        gemm(f1, w2 + (size_t)l * FF_SZ * D_SZ, x, BT, D_SZ, FF_SZ, FF_SZ, D_SZ, D_SZ,
             0, 0, 0, 0, 0, 0, 1, 1, 1);
    }

    // 4) final norm + lm_head
    rmsnorm_kernel<<<BT, 256>>>(x, final_norm, h);
    gemm(h, lm_head, out, BT, V_SZ, D_SZ, D_SZ, V_SZ, V_SZ,
         0, 0, 0, 0, 0, 0, 1, 1, 0);
}

// round 5
// speedup vs baseline: 1.9471x; 1.3166x over previous
#include <cuda_runtime.h>
#include <math.h>

typedef unsigned short u16;
typedef unsigned int   u32;

// ---------------- problem constants ----------------
#define B_SZ 2
#define T_SZ 1024
#define D_SZ 1024
#define H_SZ 16
#define DH_SZ 64
#define FF_SZ 4096
#define L_SZ 2
#define V_SZ 32000
#define M_BLK 32
#define BS_SZ 32
#define TOPK 8
#define KEEP 128
#define EPSF 1e-6f
#define PI_D 3.14159265358979323846

// ---------------- fp32 scratch ----------------
__device__ float d_x [B_SZ*T_SZ*D_SZ];
__device__ float d_h [B_SZ*T_SZ*D_SZ];
__device__ float d_q [B_SZ*T_SZ*D_SZ];
__device__ float d_k [B_SZ*T_SZ*D_SZ];
__device__ float d_v [B_SZ*T_SZ*D_SZ];
__device__ float d_o [B_SZ*T_SZ*D_SZ];
__device__ float d_sc[(size_t)B_SZ*H_SZ*T_SZ*T_SZ];
__device__ float d_f1[B_SZ*T_SZ*FF_SZ];
__device__ float d_f3[B_SZ*T_SZ*FF_SZ];
__device__ float d_G [T_SZ*T_SZ];
__device__ float d_gk[T_SZ];
__device__ float d_rho[B_SZ*T_SZ];
__device__ int   d_sel[B_SZ*M_BLK];

// ---------------- bf16 hi/lo split planes ----------------
__device__ u16 d_xh [B_SZ*T_SZ*D_SZ],  d_xl [B_SZ*T_SZ*D_SZ];
__device__ u16 d_Gh [T_SZ*T_SZ],       d_Gl [T_SZ*T_SZ];
__device__ u16 d_hh [B_SZ*T_SZ*D_SZ],  d_hl [B_SZ*T_SZ*D_SZ];
__device__ u16 d_qh [B_SZ*T_SZ*D_SZ],  d_ql [B_SZ*T_SZ*D_SZ];
__device__ u16 d_kh [B_SZ*T_SZ*D_SZ],  d_kl [B_SZ*T_SZ*D_SZ];
__device__ u16 d_vh [B_SZ*T_SZ*D_SZ],  d_vl [B_SZ*T_SZ*D_SZ];
__device__ u16 d_sch[(size_t)B_SZ*H_SZ*T_SZ*T_SZ], d_scl[(size_t)B_SZ*H_SZ*T_SZ*T_SZ];
__device__ u16 d_oh [B_SZ*T_SZ*D_SZ],  d_ol [B_SZ*T_SZ*D_SZ];
__device__ u16 d_f1h[B_SZ*T_SZ*FF_SZ], d_f1l[B_SZ*T_SZ*FF_SZ];
__device__ u16 d_wqh[L_SZ*D_SZ*D_SZ],  d_wql[L_SZ*D_SZ*D_SZ];
__device__ u16 d_wkh[L_SZ*D_SZ*D_SZ],  d_wkl[L_SZ*D_SZ*D_SZ];
__device__ u16 d_wvh[L_SZ*D_SZ*D_SZ],  d_wvl[L_SZ*D_SZ*D_SZ];
__device__ u16 d_woh[L_SZ*D_SZ*D_SZ],  d_wol[L_SZ*D_SZ*D_SZ];
__device__ u16 d_w1h[L_SZ*D_SZ*FF_SZ], d_w1l[L_SZ*D_SZ*FF_SZ];
__device__ u16 d_w2h[L_SZ*FF_SZ*D_SZ], d_w2l[L_SZ*FF_SZ*D_SZ];
__device__ u16 d_w3h[L_SZ*D_SZ*FF_SZ], d_w3l[L_SZ*D_SZ*FF_SZ];
__device__ u16 d_lmh[(size_t)D_SZ*V_SZ], d_lml[(size_t)D_SZ*V_SZ];

// ---------------- split helpers ----------------
__device__ __forceinline__ void split2(float v0, float v1, u32 &hi, u32 &lo)
{
    asm("cvt.rn.bf16x2.f32 %0, %1, %2;" : "=r"(hi) : "f"(v1), "f"(v0));
    float h0 = __int_as_float(hi << 16);
    float h1 = __int_as_float(hi & 0xffff0000u);
    asm("cvt.rn.bf16x2.f32 %0, %1, %2;" : "=r"(lo) : "f"(v1 - h1), "f"(v0 - h0));
}

// generic elementwise split: n2 = n/2 float2 chunks
__global__ __launch_bounds__(256) void split_kernel(const float* __restrict__ in,
                                                    u32* __restrict__ hi, u32* __restrict__ lo,
                                                    long n2)
{
    long idx = (long)blockIdx.x * blockDim.x + threadIdx.x;
    if (idx >= n2) return;
    float2 v = reinterpret_cast<const float2*>(in)[idx];
    u32 h, l;
    split2(v.x, v.y, h, l);
    hi[idx] = h; lo[idx] = l;
}

#define MMA_BF16(ACC, A, B0, B1)                                                 \
    asm volatile(                                                                \
        "mma.sync.aligned.m16n8k16.row.col.f32.bf16.bf16.f32 "                   \
        "{%0,%1,%2,%3}, {%4,%5,%6,%7}, {%8,%9}, {%0,%1,%2,%3};"                  \
        : "+f"(ACC[0]), "+f"(ACC[1]), "+f"(ACC[2]), "+f"(ACC[3])                 \
        : "r"(A[0]), "r"(A[1]), "r"(A[2]), "r"(A[3]), "r"(B0), "r"(B1))

#define LDSM4(R, ADDR)                                                           \
    asm volatile("ldmatrix.sync.aligned.m8n8.x4.shared.b16 {%0,%1,%2,%3},[%4];"  \
        : "=r"(R[0]), "=r"(R[1]), "=r"(R[2]), "=r"(R[3]) : "r"(ADDR))

#define LDSM4T(R0, R1, R2, R3, ADDR)                                             \
    asm volatile("ldmatrix.sync.aligned.m8n8.x4.trans.shared.b16 {%0,%1,%2,%3},[%4];" \
        : "=r"(R0), "=r"(R1), "=r"(R2), "=r"(R3) : "r"(ADDR))

// =====================================================================
// bf16 hi/lo 3-term GEMM: C[M,N] (+)= A[M,K] @ B[K,N]   (fp32 out)
// A planes: row-major [M][K] bf16. B planes: BNK=false -> natural [K][N]
// (ldmatrix .trans), BNK=true -> row-major [N][K] (non-trans; used when the
// logical B is the transpose of a row-major array, e.g. scores B = k).
// BM=128, BK=32; BN in {128,64}; 256 threads.
// =====================================================================
#define LDA_S 40   // u16 stride (80B) for A tile and NK B tile

template<int BN, int WM, int WN, bool BNK>
__global__ __launch_bounds__(256, (BN == 64) ? 2 : 1)
void bf16_gemm_kernel(const u16* __restrict__ Ahi, const u16* __restrict__ Alo,
                      const u16* __restrict__ Bhi, const u16* __restrict__ Blo,
                      float* __restrict__ Cg,
                      int K, int lda, int ldb, int ldc,
                      long sAb, long sBb, long sCb, long sAh, long sBh, long sCh,
                      int Hdim, int beta)
{
    constexpr int BM = 128, BK = 32;
    constexpr int AM = BM / WM / 16;
    constexpr int AN = BN / WN / 8;
    constexpr int LDB_S = BNK ? LDA_S : (BN + 8);
    constexpr int A_PL  = BM * LDA_S;
    constexpr int B_PL  = BNK ? (BN * LDA_S) : (BK * LDB_S);
    constexpr int STAGE = 2 * A_PL + 2 * B_PL;

    extern __shared__ u16 sm[];

    int z = blockIdx.z, zb = z / Hdim, zh = z % Hdim;
    const u16* Ah = Ahi + zb * sAb + zh * sAh;
    const u16* Al = Alo + zb * sAb + zh * sAh;
    const u16* Bh = Bhi + zb * sBb + zh * sBh;
    const u16* Bl = Blo + zb * sBb + zh * sBh;
    float*     C  = Cg  + zb * sCb + zh * sCh;

    const int tid  = threadIdx.x, lane = tid & 31, w = tid >> 5;
    const int row0 = blockIdx.y * BM, col0 = blockIdx.x * BN;
    const int wm = w % WM, wn = w / WM;
    const int mW = wm * (BM / WM), nW = wn * (BN / WN);

    float acc[AM][AN][4];
#pragma unroll
    for (int i = 0; i < AM; i++)
#pragma unroll
        for (int j = 0; j < AN; j++)
#pragma unroll
            for (int r = 0; r < 4; r++) acc[i][j][r] = 0.f;

    auto cpa = [&](u16* dst, const u16* src) {
        u32 d = (u32)__cvta_generic_to_shared(dst);
        asm volatile("cp.async.cg.shared.global [%0],[%1],16;\n" :: "r"(d), "l"(src));
    };

    auto load_tile = [&](int s, int kt) {
        u16* base = sm + s * STAGE;
        // A: 128 x 32, 4 16B-chunks per row, 512 chunks per plane
#pragma unroll
        for (int i = 0; i < 2; i++) {
            int ch = tid + i * 256;
            int r = ch >> 2, c = ch & 3;
            size_t go = (size_t)(row0 + r) * lda + kt + c * 8;
            cpa(base + r * LDA_S + c * 8,        Ah + go);
            cpa(base + A_PL + r * LDA_S + c * 8, Al + go);
        }
        u16* bb = base + 2 * A_PL;
        if (BNK) {
            constexpr int CH = BN * 4;   // [BN][BK] rows of 4 chunks
#pragma unroll
            for (int i = 0; i < CH / 256; i++) {
                int ch = tid + i * 256;
                int r = ch >> 2, c = ch & 3;
                size_t go = (size_t)(col0 + r) * ldb + kt + c * 8;
                cpa(bb + r * LDA_S + c * 8,        Bh + go);
                cpa(bb + B_PL + r * LDA_S + c * 8, Bl + go);
            }
        } else {
            constexpr int CPR = BN / 8;  // [BK][BN]
            constexpr int CH  = BK * CPR;
#pragma unroll
            for (int i = 0; i < CH / 256; i++) {
                int ch = tid + i * 256;
                int r = ch / CPR, c = ch % CPR;
                size_t go = (size_t)(kt + r) * ldb + col0 + c * 8;
                cpa(bb + r * LDB_S + c * 8,        Bh + go);
                cpa(bb + B_PL + r * LDB_S + c * 8, Bl + go);
            }
        }
    };

    load_tile(0, 0);
    asm volatile("cp.async.commit_group;\n" ::: "memory");

    const int ntiles = K / BK;
    for (int t = 0; t < ntiles; t++) {
        int s = t & 1;
        if (t + 1 < ntiles) {
            load_tile(s ^ 1, (t + 1) * BK);
            asm volatile("cp.async.commit_group;\n" ::: "memory");
            asm volatile("cp.async.wait_group 1;\n" ::: "memory");
        } else {
            asm volatile("cp.async.wait_group 0;\n" ::: "memory");
        }
        __syncthreads();

        const u16* sa = sm + s * STAGE;
        const u16* sb = sa + 2 * A_PL;

#pragma unroll
        for (int ks = 0; ks < 2; ks++) {
            u32 ah[AM][4], al[AM][4], bh[AN][2], bl[AN][2];

            // ---- A fragments (x4 ldmatrix per m16 atom, per plane) ----
            int arow = ((lane >> 3) & 1) * 8 + (lane & 7);
            int acol = ks * 16 + (lane >> 4) * 8;
#pragma unroll
            for (int am = 0; am < AM; am++) {
                const u16* p = sa + (mW + am * 16 + arow) * LDA_S + acol;
                u32 addr = (u32)__cvta_generic_to_shared(p);
                LDSM4(ah[am], addr);
                LDSM4(al[am], addr + A_PL * 2);
            }
            // ---- B fragments (x4 covers two n8 atoms) ----
            if (BNK) {
                int brow = ((lane >> 4) & 1) * 8 + (lane & 7);
                int bcol = ks * 16 + ((lane >> 3) & 1) * 8;
#pragma unroll
                for (int a2 = 0; a2 < AN / 2; a2++) {
                    const u16* p = sb + (nW + a2 * 16 + brow) * LDA_S + bcol;
                    u32 addr = (u32)__cvta_generic_to_shared(p);
                    LDSM4T(bh[2*a2][0], bh[2*a2][1], bh[2*a2+1][0], bh[2*a2+1][1], addr);
                    // non-trans here: [n][k] layout pairs with plain x4
                    asm volatile("ldmatrix.sync.aligned.m8n8.x4.shared.b16 {%0,%1,%2,%3},[%4];"
                        : "=r"(bh[2*a2][0]), "=r"(bh[2*a2][1]),
                          "=r"(bh[2*a2+1][0]), "=r"(bh[2*a2+1][1]) : "r"(addr));
                    asm volatile("ldmatrix.sync.aligned.m8n8.x4.shared.b16 {%0,%1,%2,%3},[%4];"
                        : "=r"(bl[2*a2][0]), "=r"(bl[2*a2][1]),
                          "=r"(bl[2*a2+1][0]), "=r"(bl[2*a2+1][1]) : "r"(addr + B_PL * 2));
                }
            } else {
                int brow = ks * 16 + ((lane >> 3) & 1) * 8 + (lane & 7);
                int bcol = (lane >> 4) * 8;
#pragma unroll
                for (int a2 = 0; a2 < AN / 2; a2++) {
                    const u16* p = sb + brow * LDB_S + nW + a2 * 16 + bcol;
                    u32 addr = (u32)__cvta_generic_to_shared(p);
                    LDSM4T(bh[2*a2][0], bh[2*a2][1], bh[2*a2+1][0], bh[2*a2+1][1], addr);
                    LDSM4T(bl[2*a2][0], bl[2*a2][1], bl[2*a2+1][0], bl[2*a2+1][1],
                           addr + B_PL * 2);
                }
            }

            // ---- 3-term MMA ----
#pragma unroll
            for (int am = 0; am < AM; am++)
#pragma unroll
                for (int an = 0; an < AN; an++) {
                    MMA_BF16(acc[am][an], ah[am], bh[an][0], bh[an][1]);
                    MMA_BF16(acc[am][an], ah[am], bl[an][0], bl[an][1]);
                    MMA_BF16(acc[am][an], al[am], bh[an][0], bh[an][1]);
                }
        }
        __syncthreads();
    }

    // ---- epilogue ----
#pragma unroll
    for (int am = 0; am < AM; am++)
#pragma unroll
        for (int an = 0; an < AN; an++) {
            int r = row0 + mW + am * 16 + (lane >> 2);
            int c = col0 + nW + an * 8 + (lane & 3) * 2;
            size_t i0 = (size_t)r * ldc + c;
            size_t i1 = (size_t)(r + 8) * ldc + c;
            float2 v0 = make_float2(acc[am][an][0], acc[am][an][1]);
            float2 v1 = make_float2(acc[am][an][2], acc[am][an][3]);
            if (beta) {
                float2 p0 = *reinterpret_cast<const float2*>(C + i0);
                float2 p1 = *reinterpret_cast<const float2*>(C + i1);
                v0.x += p0.x; v0.y += p0.y; v1.x += p1.x; v1.y += p1.y;
            }
            *reinterpret_cast<float2*>(C + i0) = v0;
            *reinterpret_cast<float2*>(C + i1) = v1;
        }
}

// fix: BNK branch above should use non-trans only; the stray LDSM4T is
// overwritten immediately by the correct plain x4 loads, so results are right,
// but remove redundancy by noting bh is reassigned. (Kept simple.)

// ---------------- elementwise kernels ----------------
__global__ void embed_kernel(const int* __restrict__ ids, const float* __restrict__ emb,
                             float* __restrict__ x)
{
    int idx = blockIdx.x * blockDim.x + threadIdx.x;
    int d = idx & (D_SZ - 1);
    int bt = idx >> 10;
    x[idx] = emb[(size_t)ids[bt] * D_SZ + d];
}

__global__ void dirichlet_kernel(float* __restrict__ g)
{
    int d = blockIdx.x * blockDim.x + threadIdx.x;
    if (d >= T_SZ) return;
    double s = 0.0;
    for (int k = 1; k < KEEP; k++)
        s += cos(2.0 * PI_D * (double)k * (double)d / (double)T_SZ);
    g[d] = (float)((1.0 + 2.0 * s) / (double)T_SZ);
}

__global__ void buildG_kernel(const float* __restrict__ g, float* __restrict__ G)
{
    int i = blockIdx.x * blockDim.x + threadIdx.x;
    int t = i >> 10, s = i & (T_SZ - 1);
    G[i] = g[(t - s) & (T_SZ - 1)];
}

__global__ __launch_bounds__(256) void rho_kernel(const float* __restrict__ hlp,
                                                  const float* __restrict__ x,
                                                  float* __restrict__ rho)
{
    size_t row = (size_t)blockIdx.x * D_SZ;
    int tid = threadIdx.x;
    float s1 = 0.f, s2 = 0.f;
#pragma unroll
    for (int i = 0; i < 4; i++) {
        float a = hlp[row + tid + i * 256];
        float b = x  [row + tid + i * 256];
        s1 += a * a; s2 += b * b;
    }
    for (int o = 16; o > 0; o >>= 1) {
        s1 += __shfl_xor_sync(0xffffffffu, s1, o);
        s2 += __shfl_xor_sync(0xffffffffu, s2, o);
    }
    __shared__ float r1[8], r2[8];
    if ((tid & 31) == 0) { r1[tid >> 5] = s1; r2[tid >> 5] = s2; }
    __syncthreads();
    if (tid == 0) {
        float t1 = 0.f, t2 = 0.f;
        for (int i = 0; i < 8; i++) { t1 += r1[i]; t2 += r2[i]; }
        rho[blockIdx.x] = t1 / (t2 + EPSF);
    }
}

__global__ void select_blocks(const float* __restrict__ rho, int* __restrict__ sel)
{
    __shared__ float bq[B_SZ][M_BLK];
    int tid = threadIdx.x;
    if (tid < B_SZ * M_BLK) {
        int b = tid >> 5, m = tid & 31;
        float s = 0.f;
        for (int i = 0; i < BS_SZ; i++) s += rho[b * T_SZ + m * BS_SZ + i];
        bq[b][m] = s * (1.f / BS_SZ);
        sel[tid] = 0;
    }
    __syncthreads();
    if (tid < B_SZ) {
        int b = tid;
        bool picked[M_BLK];
        for (int m = 0; m < M_BLK; m++) picked[m] = false;
        for (int it = 0; it < TOPK; it++) {
            int best = -1; float bv = -3.4e38f;
            for (int m = 0; m < M_BLK; m++)
                if (!picked[m] && bq[b][m] > bv) { bv = bq[b][m]; best = m; }
            picked[best] = true;
            sel[b * M_BLK + best] = 1;
        }
    }
}

// RMSNorm writing fp32 + split planes
__global__ __launch_bounds__(256) void rmsnorm_split_kernel(
    const float* __restrict__ x, const float* __restrict__ w,
    u32* __restrict__ yh, u32* __restrict__ yl)
{
    size_t row = (size_t)blockIdx.x * D_SZ;
    int tid = threadIdx.x;
    float4 v = reinterpret_cast<const float4*>(x + row)[tid];
    float s = v.x * v.x + v.y * v.y + v.z * v.z + v.w * v.w;
    for (int o = 16; o > 0; o >>= 1) s += __shfl_xor_sync(0xffffffffu, s, o);
    __shared__ float red[8];
    if ((tid & 31) == 0) red[tid >> 5] = s;
    __syncthreads();
    float tot = 0.f;
    for (int i = 0; i < 8; i++) tot += red[i];
    float r = rsqrtf(tot * (1.f / D_SZ) + EPSF);
    float4 wv = reinterpret_cast<const float4*>(w)[tid];
    float y0 = v.x * r * wv.x, y1 = v.y * r * wv.y;
    float y2 = v.z * r * wv.z, y3 = v.w * r * wv.w;
    u32 h0, l0, h1, l1;
    split2(y0, y1, h0, l0);
    split2(y2, y3, h1, l1);
    size_t c = row / 2 + tid * 2;
    yh[c] = h0; yh[c + 1] = h1;
    yl[c] = l0; yl[c + 1] = l1;
}

__global__ void rope_kernel(float* __restrict__ q, float* __restrict__ k)
{
    int idx = blockIdx.x * blockDim.x + threadIdx.x;
    int j = idx & 31;
    int h = (idx >> 5) & (H_SZ - 1);
    int t = (idx >> 9) & (T_SZ - 1);
    int b = idx >> 19;
    float inv = (float)(1.0 / pow(10000.0, (double)(2 * j) / (double)DH_SZ));
    float fr = (float)t * inv;
    float c = cosf(fr), s = sinf(fr);
    size_t base = ((size_t)(b * T_SZ + t)) * D_SZ + h * DH_SZ + j;
    float q0 = q[base], q1 = q[base + 32];
    q[base]      = q0 * c - q1 * s;
    q[base + 32] = q1 * c + q0 * s;
    float k0 = k[base], k1 = k[base + 32];
    k[base]      = k0 * c - k1 * s;
    k[base + 32] = k1 * c + k0 * s;
}

__global__ __launch_bounds__(256) void masked_softmax_kernel(float* __restrict__ s,
                                                             const int* __restrict__ sel)
{
    int gid = blockIdx.x;
    int tq = gid & (T_SZ - 1);
    int b  = gid / (H_SZ * T_SZ);
    size_t row = (size_t)gid * T_SZ;
    int tid = threadIdx.x;
    const float scale = 0.125f;
    int qblk = tq >> 5;

    float v[4];
    float mx = -3.4e38f;
#pragma unroll
    for (int i = 0; i < 4; i++) {
        int ts = tid + i * 256;
        bool allowed = (ts <= tq) &&
                       (sel[b * M_BLK + (ts >> 5)] || ((ts >> 5) == qblk));
        v[i] = s[row + ts] * scale + (allowed ? 0.f : -1e9f);
        mx = fmaxf(mx, v[i]);
    }
    for (int o = 16; o > 0; o >>= 1) mx = fmaxf(mx, __shfl_xor_sync(0xffffffffu, mx, o));
    __shared__ float red[8];
    if ((tid & 31) == 0) red[tid >> 5] = mx;
    __syncthreads();
    float m = red[0];
    for (int i = 1; i < 8; i++) m = fmaxf(m, red[i]);
    __syncthreads();
    float sum = 0.f;
#pragma unroll
    for (int i = 0; i < 4; i++) { v[i] = expf(v[i] - m); sum += v[i]; }
    for (int o = 16; o > 0; o >>= 1) sum += __shfl_xor_sync(0xffffffffu, sum, o);
    if ((tid & 31) == 0) red[tid >> 5] = sum;
    __syncthreads();
    float tot = 0.f;
    for (int i = 0; i < 8; i++) tot += red[i];
    float inv = 1.f / tot;
#pragma unroll
    for (int i = 0; i < 4; i++) s[row + tid + i * 256] = v[i] * inv;
}

__global__ void silu_mul_kernel(float* __restrict__ f1, const float* __restrict__ f3)
{
    int idx = blockIdx.x * blockDim.x + threadIdx.x;
    float a = f1[idx];
    f1[idx] = a / (1.f + expf(-a)) * f3[idx];
}

// ---------------- host launchers ----------------
static const int SMEM_KN128 = (2*128*LDA_S + 2*32*(128+8)) * 2 * 2;  // bytes
static const int SMEM_KN64  = (2*128*LDA_S + 2*32*(64+8))  * 2 * 2;
static const int SMEM_NK64  = (2*128*LDA_S + 2*64*LDA_S)   * 2 * 2;

static void gemm_kn(const u16* Ah, const u16* Al, const u16* Bh, const u16* Bl, float* C,
                    int M, int N, int K, int lda, int ldb, int ldc,
                    long sAb, long sBb, long sCb, long sAh, long sBh, long sCh,
                    int Hdim, int nb, int beta)
{
    if (N % 128 == 0 && N >= 4096) {
        dim3 grid(N / 128, M / 128, nb);
        bf16_gemm_kernel<128, 2, 4, false><<<grid, 256, SMEM_KN128>>>(
            Ah, Al, Bh, Bl, C, K, lda, ldb, ldc, sAb, sBb, sCb, sAh, sBh, sCh, Hdim, beta);
    } else {
        dim3 grid(N / 64, M / 128, nb);
        bf16_gemm_kernel<64, 4, 2, false><<<grid, 256, SMEM_KN64>>>(
            Ah, Al, Bh, Bl, C, K, lda, ldb, ldc, sAb, sBb, sCb, sAh, sBh, sCh, Hdim, beta);
    }
}

static void gemm_nk(const u16* Ah, const u16* Al, const u16* Bh, const u16* Bl, float* C,
                    int M, int N, int K, int lda, int ldb, int ldc,
                    long sAb, long sBb, long sCb, long sAh, long sBh, long sCh,
                    int Hdim, int nb, int beta)
{
    dim3 grid(N / 64, M / 128, nb);
    bf16_gemm_kernel<64, 4, 2, true><<<grid, 256, SMEM_NK64>>>(
        Ah, Al, Bh, Bl, C, K, lda, ldb, ldc, sAb, sBb, sCb, sAh, sBh, sCh, Hdim, beta);
}

static void split(const float* in, u16* hi, u16* lo, long n)
{
    long n2 = n / 2;
    split_kernel<<<(unsigned)((n2 + 255) / 256), 256>>>(in, (u32*)hi, (u32*)lo, n2);
}

extern "C" void kernel_launch(void* const* d_in, const int* in_sizes, int n_in,
                              void* d_out, int out_size)
{
    const int*   ids        = (const int*)  d_in[0];
    const float* emb        = (const float*)d_in[1];
    const float* wq         = (const float*)d_in[2];
    const float* wk         = (const float*)d_in[3];
    const float* wv         = (const float*)d_in[4];
    const float* wo         = (const float*)d_in[5];
    const float* w1         = (const float*)d_in[6];
    const float* w2         = (const float*)d_in[7];
    const float* w3         = (const float*)d_in[8];
    const float* attn_norm  = (const float*)d_in[9];
    const float* ffn_norm   = (const float*)d_in[10];
    const float* final_norm = (const float*)d_in[11];
    const float* lm_head    = (const float*)d_in[12];
    float* out = (float*)d_out;

    static bool attrs_set = false;
    if (!attrs_set) {
        cudaFuncSetAttribute(bf16_gemm_kernel<128, 2, 4, false>,
                             cudaFuncAttributeMaxDynamicSharedMemorySize, SMEM_KN128);
        cudaFuncSetAttribute(bf16_gemm_kernel<64, 4, 2, false>,
                             cudaFuncAttributeMaxDynamicSharedMemorySize, SMEM_KN64);
        cudaFuncSetAttribute(bf16_gemm_kernel<64, 4, 2, true>,
                             cudaFuncAttributeMaxDynamicSharedMemorySize, SMEM_NK64);
        attrs_set = true;
    }

    float *x, *h, *q, *k, *v, *o, *sc, *f1, *f3, *G, *gk, *rho;
    int* sel;
    cudaGetSymbolAddress((void**)&x,   d_x);
    cudaGetSymbolAddress((void**)&h,   d_h);
    cudaGetSymbolAddress((void**)&q,   d_q);
    cudaGetSymbolAddress((void**)&k,   d_k);
    cudaGetSymbolAddress((void**)&v,   d_v);
    cudaGetSymbolAddress((void**)&o,   d_o);
    cudaGetSymbolAddress((void**)&sc,  d_sc);
    cudaGetSymbolAddress((void**)&f1,  d_f1);
    cudaGetSymbolAddress((void**)&f3,  d_f3);
    cudaGetSymbolAddress((void**)&G,   d_G);
    cudaGetSymbolAddress((void**)&gk,  d_gk);
    cudaGetSymbolAddress((void**)&rho, d_rho);
    cudaGetSymbolAddress((void**)&sel, d_sel);

    u16 *xh,*xl,*Gh,*Gl,*hh,*hl,*qh,*ql,*kh,*kl,*vh,*vl,*sch,*scl,*oh,*ol,*f1h,*f1l;
    u16 *wqh,*wql,*wkh,*wkl,*wvh,*wvl,*woh,*wol,*w1h,*w1l,*w2h,*w2l,*w3h,*w3l,*lmh,*lml;
    cudaGetSymbolAddress((void**)&xh, d_xh);   cudaGetSymbolAddress((void**)&xl, d_xl);
    cudaGetSymbolAddress((void**)&Gh, d_Gh);   cudaGetSymbolAddress((void**)&Gl, d_Gl);
    cudaGetSymbolAddress((void**)&hh, d_hh);   cudaGetSymbolAddress((void**)&hl, d_hl);
    cudaGetSymbolAddress((void**)&qh, d_qh);   cudaGetSymbolAddress((void**)&ql, d_ql);
    cudaGetSymbolAddress((void**)&kh, d_kh);   cudaGetSymbolAddress((void**)&kl, d_kl);
    cudaGetSymbolAddress((void**)&vh, d_vh);   cudaGetSymbolAddress((void**)&vl, d_vl);
    cudaGetSymbolAddress((void**)&sch, d_sch); cudaGetSymbolAddress((void**)&scl, d_scl);
    cudaGetSymbolAddress((void**)&oh, d_oh);   cudaGetSymbolAddress((void**)&ol, d_ol);
    cudaGetSymbolAddress((void**)&f1h, d_f1h); cudaGetSymbolAddress((void**)&f1l, d_f1l);
    cudaGetSymbolAddress((void**)&wqh, d_wqh); cudaGetSymbolAddress((void**)&wql, d_wql);
    cudaGetSymbolAddress((void**)&wkh, d_wkh); cudaGetSymbolAddress((void**)&wkl, d_wkl);
    cudaGetSymbolAddress((void**)&wvh, d_wvh); cudaGetSymbolAddress((void**)&wvl, d_wvl);
    cudaGetSymbolAddress((void**)&woh, d_woh); cudaGetSymbolAddress((void**)&wol, d_wol);
    cudaGetSymbolAddress((void**)&w1h, d_w1h); cudaGetSymbolAddress((void**)&w1l, d_w1l);
    cudaGetSymbolAddress((void**)&w2h, d_w2h); cudaGetSymbolAddress((void**)&w2l, d_w2l);
    cudaGetSymbolAddress((void**)&w3h, d_w3h); cudaGetSymbolAddress((void**)&w3l, d_w3l);
    cudaGetSymbolAddress((void**)&lmh, d_lmh); cudaGetSymbolAddress((void**)&lml, d_lml);

    const int  BT = B_SZ * T_SZ;
    const long DD = (long)D_SZ * D_SZ;
    const long DF = (long)D_SZ * FF_SZ;

    // weight splits (graph-replayed each iteration; cheap vs GEMM savings)
    split(wq, wqh, wql, (long)L_SZ * DD);
    split(wk, wkh, wkl, (long)L_SZ * DD);
    split(wv, wvh, wvl, (long)L_SZ * DD);
    split(wo, woh, wol, (long)L_SZ * DD);
    split(w1, w1h, w1l, (long)L_SZ * DF);
    split(w2, w2h, w2l, (long)L_SZ * DF);
    split(w3, w3h, w3l, (long)L_SZ * DF);
    split(lm_head, lmh, lml, (long)D_SZ * V_SZ);

    // 1) embedding
    embed_kernel<<<(B_SZ * T_SZ * D_SZ) / 256, 256>>>(ids, emb, x);
    split(x, xh, xl, (long)BT * D_SZ);

    // 2) low-pass quality -> block selection
    dirichlet_kernel<<<T_SZ / 256, 256>>>(gk);
    buildG_kernel<<<(T_SZ * T_SZ) / 256, 256>>>(gk, G);
    split(G, Gh, Gl, (long)T_SZ * T_SZ);
    gemm_kn(Gh, Gl, xh, xl, h, T_SZ, D_SZ, T_SZ, T_SZ, D_SZ, D_SZ,
            0, (long)T_SZ * D_SZ, (long)T_SZ * D_SZ, 0, 0, 0, 1, B_SZ, 0);
    rho_kernel<<<BT, 256>>>(h, x, rho);
    select_blocks<<<1, 64>>>(rho, sel);

    // 3) transformer layers
    for (int l = 0; l < L_SZ; l++) {
        rmsnorm_split_kernel<<<BT, 256>>>(x, attn_norm + (size_t)l * D_SZ, (u32*)hh, (u32*)hl);

        gemm_kn(hh, hl, wqh + l * DD, wql + l * DD, q, BT, D_SZ, D_SZ, D_SZ, D_SZ, D_SZ,
                0, 0, 0, 0, 0, 0, 1, 1, 0);
        gemm_kn(hh, hl, wkh + l * DD, wkl + l * DD, k, BT, D_SZ, D_SZ, D_SZ, D_SZ, D_SZ,
                0, 0, 0, 0, 0, 0, 1, 1, 0);
        gemm_kn(hh, hl, wvh + l * DD, wvl + l * DD, v, BT, D_SZ, D_SZ, D_SZ, D_SZ, D_SZ,
                0, 0, 0, 0, 0, 0, 1, 1, 0);

        rope_kernel<<<(B_SZ * T_SZ * H_SZ * 32) / 256, 256>>>(q, k);
        split(q, qh, ql, (long)BT * D_SZ);
        split(k, kh, kl, (long)BT * D_SZ);
        split(v, vh, vl, (long)BT * D_SZ);

        // scores[b,h] = q_head @ k_head^T : B = k rows (NK layout)
        gemm_nk(qh, ql, kh, kl, sc, T_SZ, T_SZ, DH_SZ, D_SZ, D_SZ, T_SZ,
                (long)T_SZ * D_SZ, (long)T_SZ * D_SZ, (long)H_SZ * T_SZ * T_SZ,
                DH_SZ, DH_SZ, (long)T_SZ * T_SZ, H_SZ, B_SZ * H_SZ, 0);

        masked_softmax_kernel<<<B_SZ * H_SZ * T_SZ, 256>>>(sc, sel);
        split(sc, sch, scl, (long)B_SZ * H_SZ * T_SZ * T_SZ);

        // o_head = attn @ v_head (v natural KN layout)
        gemm_kn(sch, scl, vh, vl, o, T_SZ, DH_SZ, T_SZ, T_SZ, D_SZ, D_SZ,
                (long)H_SZ * T_SZ * T_SZ, (long)T_SZ * D_SZ, (long)T_SZ * D_SZ,
                (long)T_SZ * T_SZ, DH_SZ, DH_SZ, H_SZ, B_SZ * H_SZ, 0);

        split(o, oh, ol, (long)BT * D_SZ);
        gemm_kn(oh, ol, woh + l * DD, wol + l * DD, x, BT, D_SZ, D_SZ, D_SZ, D_SZ, D_SZ,
                0, 0, 0, 0, 0, 0, 1, 1, 1);

        // FFN
        rmsnorm_split_kernel<<<BT, 256>>>(x, ffn_norm + (size_t)l * D_SZ, (u32*)hh, (u32*)hl);
        gemm_kn(hh, hl, w1h + l * DF, w1l + l * DF, f1, BT, FF_SZ, D_SZ, D_SZ, FF_SZ, FF_SZ,
                0, 0, 0, 0, 0, 0, 1, 1, 0);
        gemm_kn(hh, hl, w3h + l * DF, w3l + l * DF, f3, BT, FF_SZ, D_SZ, D_SZ, FF_SZ, FF_SZ,
                0, 0, 0, 0, 0, 0, 1, 1, 0);
        silu_mul_kernel<<<(BT * FF_SZ) / 256, 256>>>(f1, f3);
        split(f1, f1h, f1l, (long)BT * FF_SZ);
        gemm_kn(f1h, f1l, w2h + l * DF, w2l + l * DF, x, BT, D_SZ, FF_SZ, FF_SZ, D_SZ, D_SZ,
                0, 0, 0, 0, 0, 0, 1, 1, 1);
    }

    // 4) final norm + lm_head
    rmsnorm_split_kernel<<<BT, 256>>>(x, final_norm, (u32*)hh, (u32*)hl);
    gemm_kn(hh, hl, lmh, lml, out, BT, V_SZ, D_SZ, D_SZ, V_SZ, V_SZ,
            0, 0, 0, 0, 0, 0, 1, 1, 0);
}

// round 6
// speedup vs baseline: 1.9511x; 1.0021x over previous
#include <cuda_runtime.h>
#include <math.h>

typedef unsigned short u16;
typedef unsigned int   u32;

// ---------------- problem constants ----------------
#define B_SZ 2
#define T_SZ 1024
#define D_SZ 1024
#define H_SZ 16
#define DH_SZ 64
#define FF_SZ 4096
#define L_SZ 2
#define V_SZ 32000
#define M_BLK 32
#define BS_SZ 32
#define TOPK 8
#define KEEP 128
#define EPSF 1e-6f
#define PI_D 3.14159265358979323846

// ---------------- fp32 scratch ----------------
__device__ float d_x [B_SZ*T_SZ*D_SZ];
__device__ float d_h [B_SZ*T_SZ*D_SZ];
__device__ float d_q [B_SZ*T_SZ*D_SZ];
__device__ float d_k [B_SZ*T_SZ*D_SZ];
__device__ float d_v [B_SZ*T_SZ*D_SZ];
__device__ float d_o [B_SZ*T_SZ*D_SZ];
__device__ float d_sc[(size_t)B_SZ*H_SZ*T_SZ*T_SZ];
__device__ float d_f1[B_SZ*T_SZ*FF_SZ];
__device__ float d_f3[B_SZ*T_SZ*FF_SZ];
__device__ float d_G [T_SZ*T_SZ];
__device__ float d_gk[T_SZ];
__device__ float d_rho[B_SZ*T_SZ];
__device__ int   d_sel[B_SZ*M_BLK];

// ---------------- bf16 hi/lo split planes ----------------
__device__ u16 d_xh [B_SZ*T_SZ*D_SZ],  d_xl [B_SZ*T_SZ*D_SZ];
__device__ u16 d_Gh [T_SZ*T_SZ],       d_Gl [T_SZ*T_SZ];
__device__ u16 d_hh [B_SZ*T_SZ*D_SZ],  d_hl [B_SZ*T_SZ*D_SZ];
__device__ u16 d_qh [B_SZ*T_SZ*D_SZ],  d_ql [B_SZ*T_SZ*D_SZ];
__device__ u16 d_kh [B_SZ*T_SZ*D_SZ],  d_kl [B_SZ*T_SZ*D_SZ];
__device__ u16 d_vh [B_SZ*T_SZ*D_SZ],  d_vl [B_SZ*T_SZ*D_SZ];
__device__ u16 d_sch[(size_t)B_SZ*H_SZ*T_SZ*T_SZ], d_scl[(size_t)B_SZ*H_SZ*T_SZ*T_SZ];
__device__ u16 d_oh [B_SZ*T_SZ*D_SZ],  d_ol [B_SZ*T_SZ*D_SZ];
__device__ u16 d_f1h[B_SZ*T_SZ*FF_SZ], d_f1l[B_SZ*T_SZ*FF_SZ];
__device__ u16 d_wqh[L_SZ*D_SZ*D_SZ],  d_wql[L_SZ*D_SZ*D_SZ];
__device__ u16 d_wkh[L_SZ*D_SZ*D_SZ],  d_wkl[L_SZ*D_SZ*D_SZ];
__device__ u16 d_wvh[L_SZ*D_SZ*D_SZ],  d_wvl[L_SZ*D_SZ*D_SZ];
__device__ u16 d_woh[L_SZ*D_SZ*D_SZ],  d_wol[L_SZ*D_SZ*D_SZ];
__device__ u16 d_w1h[L_SZ*D_SZ*FF_SZ], d_w1l[L_SZ*D_SZ*FF_SZ];
__device__ u16 d_w2h[L_SZ*FF_SZ*D_SZ], d_w2l[L_SZ*FF_SZ*D_SZ];
__device__ u16 d_w3h[L_SZ*D_SZ*FF_SZ], d_w3l[L_SZ*D_SZ*FF_SZ];
__device__ u16 d_lmh[(size_t)D_SZ*V_SZ], d_lml[(size_t)D_SZ*V_SZ];

// ---------------- split helpers ----------------
__device__ __forceinline__ void split2(float v0, float v1, u32 &hi, u32 &lo)
{
    asm("cvt.rn.bf16x2.f32 %0, %1, %2;" : "=r"(hi) : "f"(v1), "f"(v0));
    float h0 = __int_as_float(hi << 16);
    float h1 = __int_as_float(hi & 0xffff0000u);
    asm("cvt.rn.bf16x2.f32 %0, %1, %2;" : "=r"(lo) : "f"(v1 - h1), "f"(v0 - h0));
}

// generic elementwise split: n2 = n/2 float2 chunks
__global__ __launch_bounds__(256) void split_kernel(const float* __restrict__ in,
                                                    u32* __restrict__ hi, u32* __restrict__ lo,
                                                    long n2)
{
    long idx = (long)blockIdx.x * blockDim.x + threadIdx.x;
    if (idx >= n2) return;
    float2 v = reinterpret_cast<const float2*>(in)[idx];
    u32 h, l;
    split2(v.x, v.y, h, l);
    hi[idx] = h; lo[idx] = l;
}

#define MMA_BF16(ACC, A, B0, B1)                                                 \
    asm volatile(                                                                \
        "mma.sync.aligned.m16n8k16.row.col.f32.bf16.bf16.f32 "                   \
        "{%0,%1,%2,%3}, {%4,%5,%6,%7}, {%8,%9}, {%0,%1,%2,%3};"                  \
        : "+f"(ACC[0]), "+f"(ACC[1]), "+f"(ACC[2]), "+f"(ACC[3])                 \
        : "r"(A[0]), "r"(A[1]), "r"(A[2]), "r"(A[3]), "r"(B0), "r"(B1))

#define LDSM4(R, ADDR)                                                           \
    asm volatile("ldmatrix.sync.aligned.m8n8.x4.shared.b16 {%0,%1,%2,%3},[%4];"  \
        : "=r"(R[0]), "=r"(R[1]), "=r"(R[2]), "=r"(R[3]) : "r"(ADDR))

#define LDSM4T(R0, R1, R2, R3, ADDR)                                             \
    asm volatile("ldmatrix.sync.aligned.m8n8.x4.trans.shared.b16 {%0,%1,%2,%3},[%4];" \
        : "=r"(R0), "=r"(R1), "=r"(R2), "=r"(R3) : "r"(ADDR))

// =====================================================================
// bf16 hi/lo 3-term GEMM: C[M,N] (+)= A[M,K] @ B[K,N]   (fp32 out)
// A planes: row-major [M][K] bf16. B planes: BNK=false -> natural [K][N]
// (ldmatrix .trans), BNK=true -> row-major [N][K] (non-trans; used when the
// logical B is the transpose of a row-major array, e.g. scores B = k).
// BM=128, BK=32; BN in {128,64}; 256 threads.
// =====================================================================
#define LDA_S 40   // u16 stride (80B) for A tile and NK B tile

template<int BN, int WM, int WN, bool BNK>
__global__ __launch_bounds__(256, (BN == 64) ? 2 : 1)
void bf16_gemm_kernel(const u16* __restrict__ Ahi, const u16* __restrict__ Alo,
                      const u16* __restrict__ Bhi, const u16* __restrict__ Blo,
                      float* __restrict__ Cg,
                      int K, int lda, int ldb, int ldc,
                      long sAb, long sBb, long sCb, long sAh, long sBh, long sCh,
                      int Hdim, int beta)
{
    constexpr int BM = 128, BK = 32;
    constexpr int AM = BM / WM / 16;
    constexpr int AN = BN / WN / 8;
    constexpr int LDB_S = BNK ? LDA_S : (BN + 8);
    constexpr int A_PL  = BM * LDA_S;
    constexpr int B_PL  = BNK ? (BN * LDA_S) : (BK * LDB_S);
    constexpr int STAGE = 2 * A_PL + 2 * B_PL;

    extern __shared__ u16 sm[];

    int z = blockIdx.z, zb = z / Hdim, zh = z % Hdim;
    const u16* Ah = Ahi + zb * sAb + zh * sAh;
    const u16* Al = Alo + zb * sAb + zh * sAh;
    const u16* Bh = Bhi + zb * sBb + zh * sBh;
    const u16* Bl = Blo + zb * sBb + zh * sBh;
    float*     C  = Cg  + zb * sCb + zh * sCh;

    const int tid  = threadIdx.x, lane = tid & 31, w = tid >> 5;
    const int row0 = blockIdx.y * BM, col0 = blockIdx.x * BN;
    const int wm = w % WM, wn = w / WM;
    const int mW = wm * (BM / WM), nW = wn * (BN / WN);

    float acc[AM][AN][4];
#pragma unroll
    for (int i = 0; i < AM; i++)
#pragma unroll
        for (int j = 0; j < AN; j++)
#pragma unroll
            for (int r = 0; r < 4; r++) acc[i][j][r] = 0.f;

    auto cpa = [&](u16* dst, const u16* src) {
        u32 d = (u32)__cvta_generic_to_shared(dst);
        asm volatile("cp.async.cg.shared.global [%0],[%1],16;\n" :: "r"(d), "l"(src));
    };

    auto load_tile = [&](int s, int kt) {
        u16* base = sm + s * STAGE;
        // A: 128 x 32, 4 16B-chunks per row, 512 chunks per plane
#pragma unroll
        for (int i = 0; i < 2; i++) {
            int ch = tid + i * 256;
            int r = ch >> 2, c = ch & 3;
            size_t go = (size_t)(row0 + r) * lda + kt + c * 8;
            cpa(base + r * LDA_S + c * 8,        Ah + go);
            cpa(base + A_PL + r * LDA_S + c * 8, Al + go);
        }
        u16* bb = base + 2 * A_PL;
        if (BNK) {
            constexpr int CH = BN * 4;   // [BN][BK] rows of 4 chunks
#pragma unroll
            for (int i = 0; i < CH / 256; i++) {
                int ch = tid + i * 256;
                int r = ch >> 2, c = ch & 3;
                size_t go = (size_t)(col0 + r) * ldb + kt + c * 8;
                cpa(bb + r * LDA_S + c * 8,        Bh + go);
                cpa(bb + B_PL + r * LDA_S + c * 8, Bl + go);
            }
        } else {
            constexpr int CPR = BN / 8;  // [BK][BN]
            constexpr int CH  = BK * CPR;
#pragma unroll
            for (int i = 0; i < CH / 256; i++) {
                int ch = tid + i * 256;
                int r = ch / CPR, c = ch % CPR;
                size_t go = (size_t)(kt + r) * ldb + col0 + c * 8;
                cpa(bb + r * LDB_S + c * 8,        Bh + go);
                cpa(bb + B_PL + r * LDB_S + c * 8, Bl + go);
            }
        }
    };

    load_tile(0, 0);
    asm volatile("cp.async.commit_group;\n" ::: "memory");

    const int ntiles = K / BK;
    for (int t = 0; t < ntiles; t++) {
        int s = t & 1;
        if (t + 1 < ntiles) {
            load_tile(s ^ 1, (t + 1) * BK);
            asm volatile("cp.async.commit_group;\n" ::: "memory");
            asm volatile("cp.async.wait_group 1;\n" ::: "memory");
        } else {
            asm volatile("cp.async.wait_group 0;\n" ::: "memory");
        }
        __syncthreads();

        const u16* sa = sm + s * STAGE;
        const u16* sb = sa + 2 * A_PL;

#pragma unroll
        for (int ks = 0; ks < 2; ks++) {
            u32 ah[AM][4], al[AM][4], bh[AN][2], bl[AN][2];

            // ---- A fragments (x4 ldmatrix per m16 atom, per plane) ----
            int arow = ((lane >> 3) & 1) * 8 + (lane & 7);
            int acol = ks * 16 + (lane >> 4) * 8;
#pragma unroll
            for (int am = 0; am < AM; am++) {
                const u16* p = sa + (mW + am * 16 + arow) * LDA_S + acol;
                u32 addr = (u32)__cvta_generic_to_shared(p);
                LDSM4(ah[am], addr);
                LDSM4(al[am], addr + A_PL * 2);
            }
            // ---- B fragments (x4 covers two n8 atoms) ----
            if (BNK) {
                int brow = ((lane >> 4) & 1) * 8 + (lane & 7);
                int bcol = ks * 16 + ((lane >> 3) & 1) * 8;
#pragma unroll
                for (int a2 = 0; a2 < AN / 2; a2++) {
                    const u16* p = sb + (nW + a2 * 16 + brow) * LDA_S + bcol;
                    u32 addr = (u32)__cvta_generic_to_shared(p);
                    LDSM4T(bh[2*a2][0], bh[2*a2][1], bh[2*a2+1][0], bh[2*a2+1][1], addr);
                    // non-trans here: [n][k] layout pairs with plain x4
                    asm volatile("ldmatrix.sync.aligned.m8n8.x4.shared.b16 {%0,%1,%2,%3},[%4];"
                        : "=r"(bh[2*a2][0]), "=r"(bh[2*a2][1]),
                          "=r"(bh[2*a2+1][0]), "=r"(bh[2*a2+1][1]) : "r"(addr));
                    asm volatile("ldmatrix.sync.aligned.m8n8.x4.shared.b16 {%0,%1,%2,%3},[%4];"
                        : "=r"(bl[2*a2][0]), "=r"(bl[2*a2][1]),
                          "=r"(bl[2*a2+1][0]), "=r"(bl[2*a2+1][1]) : "r"(addr + B_PL * 2));
                }
            } else {
                int brow = ks * 16 + ((lane >> 3) & 1) * 8 + (lane & 7);
                int bcol = (lane >> 4) * 8;
#pragma unroll
                for (int a2 = 0; a2 < AN / 2; a2++) {
                    const u16* p = sb + brow * LDB_S + nW + a2 * 16 + bcol;
                    u32 addr = (u32)__cvta_generic_to_shared(p);
                    LDSM4T(bh[2*a2][0], bh[2*a2][1], bh[2*a2+1][0], bh[2*a2+1][1], addr);
                    LDSM4T(bl[2*a2][0], bl[2*a2][1], bl[2*a2+1][0], bl[2*a2+1][1],
                           addr + B_PL * 2);
                }
            }

            // ---- 3-term MMA ----
#pragma unroll
            for (int am = 0; am < AM; am++)
#pragma unroll
                for (int an = 0; an < AN; an++) {
                    MMA_BF16(acc[am][an], ah[am], bh[an][0], bh[an][1]);
                    MMA_BF16(acc[am][an], ah[am], bl[an][0], bl[an][1]);
                    MMA_BF16(acc[am][an], al[am], bh[an][0], bh[an][1]);
                }
        }
        __syncthreads();
    }

    // ---- epilogue ----
#pragma unroll
    for (int am = 0; am < AM; am++)
#pragma unroll
        for (int an = 0; an < AN; an++) {
            int r = row0 + mW + am * 16 + (lane >> 2);
            int c = col0 + nW + an * 8 + (lane & 3) * 2;
            size_t i0 = (size_t)r * ldc + c;
            size_t i1 = (size_t)(r + 8) * ldc + c;
            float2 v0 = make_float2(acc[am][an][0], acc[am][an][1]);
            float2 v1 = make_float2(acc[am][an][2], acc[am][an][3]);
            if (beta) {
                float2 p0 = *reinterpret_cast<const float2*>(C + i0);
                float2 p1 = *reinterpret_cast<const float2*>(C + i1);
                v0.x += p0.x; v0.y += p0.y; v1.x += p1.x; v1.y += p1.y;
            }
            *reinterpret_cast<float2*>(C + i0) = v0;
            *reinterpret_cast<float2*>(C + i1) = v1;
        }
}

// fix: BNK branch above should use non-trans only; the stray LDSM4T is
// overwritten immediately by the correct plain x4 loads, so results are right,
// but remove redundancy by noting bh is reassigned. (Kept simple.)

// ---------------- elementwise kernels ----------------
__global__ void embed_kernel(const int* __restrict__ ids, const float* __restrict__ emb,
                             float* __restrict__ x)
{
    int idx = blockIdx.x * blockDim.x + threadIdx.x;
    int d = idx & (D_SZ - 1);
    int bt = idx >> 10;
    x[idx] = emb[(size_t)ids[bt] * D_SZ + d];
}

__global__ void dirichlet_kernel(float* __restrict__ g)
{
    int d = blockIdx.x * blockDim.x + threadIdx.x;
    if (d >= T_SZ) return;
    double s = 0.0;
    for (int k = 1; k < KEEP; k++)
        s += cos(2.0 * PI_D * (double)k * (double)d / (double)T_SZ);
    g[d] = (float)((1.0 + 2.0 * s) / (double)T_SZ);
}

__global__ void buildG_kernel(const float* __restrict__ g, float* __restrict__ G)
{
    int i = blockIdx.x * blockDim.x + threadIdx.x;
    int t = i >> 10, s = i & (T_SZ - 1);
    G[i] = g[(t - s) & (T_SZ - 1)];
}

__global__ __launch_bounds__(256) void rho_kernel(const float* __restrict__ hlp,
                                                  const float* __restrict__ x,
                                                  float* __restrict__ rho)
{
    size_t row = (size_t)blockIdx.x * D_SZ;
    int tid = threadIdx.x;
    float s1 = 0.f, s2 = 0.f;
#pragma unroll
    for (int i = 0; i < 4; i++) {
        float a = hlp[row + tid + i * 256];
        float b = x  [row + tid + i * 256];
        s1 += a * a; s2 += b * b;
    }
    for (int o = 16; o > 0; o >>= 1) {
        s1 += __shfl_xor_sync(0xffffffffu, s1, o);
        s2 += __shfl_xor_sync(0xffffffffu, s2, o);
    }
    __shared__ float r1[8], r2[8];
    if ((tid & 31) == 0) { r1[tid >> 5] = s1; r2[tid >> 5] = s2; }
    __syncthreads();
    if (tid == 0) {
        float t1 = 0.f, t2 = 0.f;
        for (int i = 0; i < 8; i++) { t1 += r1[i]; t2 += r2[i]; }
        rho[blockIdx.x] = t1 / (t2 + EPSF);
    }
}

__global__ void select_blocks(const float* __restrict__ rho, int* __restrict__ sel)
{
    __shared__ float bq[B_SZ][M_BLK];
    int tid = threadIdx.x;
    if (tid < B_SZ * M_BLK) {
        int b = tid >> 5, m = tid & 31;
        float s = 0.f;
        for (int i = 0; i < BS_SZ; i++) s += rho[b * T_SZ + m * BS_SZ + i];
        bq[b][m] = s * (1.f / BS_SZ);
        sel[tid] = 0;
    }
    __syncthreads();
    if (tid < B_SZ) {
        int b = tid;
        bool picked[M_BLK];
        for (int m = 0; m < M_BLK; m++) picked[m] = false;
        for (int it = 0; it < TOPK; it++) {
            int best = -1; float bv = -3.4e38f;
            for (int m = 0; m < M_BLK; m++)
                if (!picked[m] && bq[b][m] > bv) { bv = bq[b][m]; best = m; }
            picked[best] = true;
            sel[b * M_BLK + best] = 1;
        }
    }
}

// RMSNorm writing fp32 + split planes
__global__ __launch_bounds__(256) void rmsnorm_split_kernel(
    const float* __restrict__ x, const float* __restrict__ w,
    u32* __restrict__ yh, u32* __restrict__ yl)
{
    size_t row = (size_t)blockIdx.x * D_SZ;
    int tid = threadIdx.x;
    float4 v = reinterpret_cast<const float4*>(x + row)[tid];
    float s = v.x * v.x + v.y * v.y + v.z * v.z + v.w * v.w;
    for (int o = 16; o > 0; o >>= 1) s += __shfl_xor_sync(0xffffffffu, s, o);
    __shared__ float red[8];
    if ((tid & 31) == 0) red[tid >> 5] = s;
    __syncthreads();
    float tot = 0.f;
    for (int i = 0; i < 8; i++) tot += red[i];
    float r = rsqrtf(tot * (1.f / D_SZ) + EPSF);
    float4 wv = reinterpret_cast<const float4*>(w)[tid];
    float y0 = v.x * r * wv.x, y1 = v.y * r * wv.y;
    float y2 = v.z * r * wv.z, y3 = v.w * r * wv.w;
    u32 h0, l0, h1, l1;
    split2(y0, y1, h0, l0);
    split2(y2, y3, h1, l1);
    size_t c = row / 2 + tid * 2;
    yh[c] = h0; yh[c + 1] = h1;
    yl[c] = l0; yl[c + 1] = l1;
}

__global__ void rope_kernel(float* __restrict__ q, float* __restrict__ k)
{
    int idx = blockIdx.x * blockDim.x + threadIdx.x;
    int j = idx & 31;
    int h = (idx >> 5) & (H_SZ - 1);
    int t = (idx >> 9) & (T_SZ - 1);
    int b = idx >> 19;
    float inv = (float)(1.0 / pow(10000.0, (double)(2 * j) / (double)DH_SZ));
    float fr = (float)t * inv;
    float c = cosf(fr), s = sinf(fr);
    size_t base = ((size_t)(b * T_SZ + t)) * D_SZ + h * DH_SZ + j;
    float q0 = q[base], q1 = q[base + 32];
    q[base]      = q0 * c - q1 * s;
    q[base + 32] = q1 * c + q0 * s;
    float k0 = k[base], k1 = k[base + 32];
    k[base]      = k0 * c - k1 * s;
    k[base + 32] = k1 * c + k0 * s;
}

__global__ __launch_bounds__(256) void masked_softmax_kernel(float* __restrict__ s,
                                                             const int* __restrict__ sel)
{
    int gid = blockIdx.x;
    int tq = gid & (T_SZ - 1);
    int b  = gid / (H_SZ * T_SZ);
    size_t row = (size_t)gid * T_SZ;
    int tid = threadIdx.x;
    const float scale = 0.125f;
    int qblk = tq >> 5;

    float v[4];
    float mx = -3.4e38f;
#pragma unroll
    for (int i = 0; i < 4; i++) {
        int ts = tid + i * 256;
        bool allowed = (ts <= tq) &&
                       (sel[b * M_BLK + (ts >> 5)] || ((ts >> 5) == qblk));
        v[i] = s[row + ts] * scale + (allowed ? 0.f : -1e9f);
        mx = fmaxf(mx, v[i]);
    }
    for (int o = 16; o > 0; o >>= 1) mx = fmaxf(mx, __shfl_xor_sync(0xffffffffu, mx, o));
    __shared__ float red[8];
    if ((tid & 31) == 0) red[tid >> 5] = mx;
    __syncthreads();
    float m = red[0];
    for (int i = 1; i < 8; i++) m = fmaxf(m, red[i]);
    __syncthreads();
    float sum = 0.f;
#pragma unroll
    for (int i = 0; i < 4; i++) { v[i] = expf(v[i] - m); sum += v[i]; }
    for (int o = 16; o > 0; o >>= 1) sum += __shfl_xor_sync(0xffffffffu, sum, o);
    if ((tid & 31) == 0) red[tid >> 5] = sum;
    __syncthreads();
    float tot = 0.f;
    for (int i = 0; i < 8; i++) tot += red[i];
    float inv = 1.f / tot;
#pragma unroll
    for (int i = 0; i < 4; i++) s[row + tid + i * 256] = v[i] * inv;
}

__global__ void silu_mul_kernel(float* __restrict__ f1, const float* __restrict__ f3)
{
    int idx = blockIdx.x * blockDim.x + threadIdx.x;
    float a = f1[idx];
    f1[idx] = a / (1.f + expf(-a)) * f3[idx];
}

// ---------------- host launchers ----------------
static const int SMEM_KN128 = (2*128*LDA_S + 2*32*(128+8)) * 2 * 2;  // bytes
static const int SMEM_KN64  = (2*128*LDA_S + 2*32*(64+8))  * 2 * 2;
static const int SMEM_NK64  = (2*128*LDA_S + 2*64*LDA_S)   * 2 * 2;

static void gemm_kn(const u16* Ah, const u16* Al, const u16* Bh, const u16* Bl, float* C,
                    int M, int N, int K, int lda, int ldb, int ldc,
                    long sAb, long sBb, long sCb, long sAh, long sBh, long sCh,
                    int Hdim, int nb, int beta)
{
    if (N % 128 == 0 && N >= 4096) {
        dim3 grid(N / 128, M / 128, nb);
        bf16_gemm_kernel<128, 2, 4, false><<<grid, 256, SMEM_KN128>>>(
            Ah, Al, Bh, Bl, C, K, lda, ldb, ldc, sAb, sBb, sCb, sAh, sBh, sCh, Hdim, beta);
    } else {
        dim3 grid(N / 64, M / 128, nb);
        bf16_gemm_kernel<64, 4, 2, false><<<grid, 256, SMEM_KN64>>>(
            Ah, Al, Bh, Bl, C, K, lda, ldb, ldc, sAb, sBb, sCb, sAh, sBh, sCh, Hdim, beta);
    }
}

static void gemm_nk(const u16* Ah, const u16* Al, const u16* Bh, const u16* Bl, float* C,
                    int M, int N, int K, int lda, int ldb, int ldc,
                    long sAb, long sBb, long sCb, long sAh, long sBh, long sCh,
                    int Hdim, int nb, int beta)
{
    dim3 grid(N / 64, M / 128, nb);
    bf16_gemm_kernel<64, 4, 2, true><<<grid, 256, SMEM_NK64>>>(
        Ah, Al, Bh, Bl, C, K, lda, ldb, ldc, sAb, sBb, sCb, sAh, sBh, sCh, Hdim, beta);
}

static void split(const float* in, u16* hi, u16* lo, long n)
{
    long n2 = n / 2;
    split_kernel<<<(unsigned)((n2 + 255) / 256), 256>>>(in, (u32*)hi, (u32*)lo, n2);
}

extern "C" void kernel_launch(void* const* d_in, const int* in_sizes, int n_in,
                              void* d_out, int out_size)
{
    const int*   ids        = (const int*)  d_in[0];
    const float* emb        = (const float*)d_in[1];
    const float* wq         = (const float*)d_in[2];
    const float* wk         = (const float*)d_in[3];
    const float* wv         = (const float*)d_in[4];
    const float* wo         = (const float*)d_in[5];
    const float* w1         = (const float*)d_in[6];
    const float* w2         = (const float*)d_in[7];
    const float* w3         = (const float*)d_in[8];
    const float* attn_norm  = (const float*)d_in[9];
    const float* ffn_norm   = (const float*)d_in[10];
    const float* final_norm = (const float*)d_in[11];
    const float* lm_head    = (const float*)d_in[12];
    float* out = (float*)d_out;

    static bool attrs_set = false;
    if (!attrs_set) {
        cudaFuncSetAttribute(bf16_gemm_kernel<128, 2, 4, false>,
                             cudaFuncAttributeMaxDynamicSharedMemorySize, SMEM_KN128);
        cudaFuncSetAttribute(bf16_gemm_kernel<64, 4, 2, false>,
                             cudaFuncAttributeMaxDynamicSharedMemorySize, SMEM_KN64);
        cudaFuncSetAttribute(bf16_gemm_kernel<64, 4, 2, true>,
                             cudaFuncAttributeMaxDynamicSharedMemorySize, SMEM_NK64);
        attrs_set = true;
    }

    float *x, *h, *q, *k, *v, *o, *sc, *f1, *f3, *G, *gk, *rho;
    int* sel;
    cudaGetSymbolAddress((void**)&x,   d_x);
    cudaGetSymbolAddress((void**)&h,   d_h);
    cudaGetSymbolAddress((void**)&q,   d_q);
    cudaGetSymbolAddress((void**)&k,   d_k);
    cudaGetSymbolAddress((void**)&v,   d_v);
    cudaGetSymbolAddress((void**)&o,   d_o);
    cudaGetSymbolAddress((void**)&sc,  d_sc);
    cudaGetSymbolAddress((void**)&f1,  d_f1);
    cudaGetSymbolAddress((void**)&f3,  d_f3);
    cudaGetSymbolAddress((void**)&G,   d_G);
    cudaGetSymbolAddress((void**)&gk,  d_gk);
    cudaGetSymbolAddress((void**)&rho, d_rho);
    cudaGetSymbolAddress((void**)&sel, d_sel);

    u16 *xh,*xl,*Gh,*Gl,*hh,*hl,*qh,*ql,*kh,*kl,*vh,*vl,*sch,*scl,*oh,*ol,*f1h,*f1l;
    u16 *wqh,*wql,*wkh,*wkl,*wvh,*wvl,*woh,*wol,*w1h,*w1l,*w2h,*w2l,*w3h,*w3l,*lmh,*lml;
    cudaGetSymbolAddress((void**)&xh, d_xh);   cudaGetSymbolAddress((void**)&xl, d_xl);
    cudaGetSymbolAddress((void**)&Gh, d_Gh);   cudaGetSymbolAddress((void**)&Gl, d_Gl);
    cudaGetSymbolAddress((void**)&hh, d_hh);   cudaGetSymbolAddress((void**)&hl, d_hl);
    cudaGetSymbolAddress((void**)&qh, d_qh);   cudaGetSymbolAddress((void**)&ql, d_ql);
    cudaGetSymbolAddress((void**)&kh, d_kh);   cudaGetSymbolAddress((void**)&kl, d_kl);
    cudaGetSymbolAddress((void**)&vh, d_vh);   cudaGetSymbolAddress((void**)&vl, d_vl);
    cudaGetSymbolAddress((void**)&sch, d_sch); cudaGetSymbolAddress((void**)&scl, d_scl);
    cudaGetSymbolAddress((void**)&oh, d_oh);   cudaGetSymbolAddress((void**)&ol, d_ol);
    cudaGetSymbolAddress((void**)&f1h, d_f1h); cudaGetSymbolAddress((void**)&f1l, d_f1l);
    cudaGetSymbolAddress((void**)&wqh, d_wqh); cudaGetSymbolAddress((void**)&wql, d_wql);
    cudaGetSymbolAddress((void**)&wkh, d_wkh); cudaGetSymbolAddress((void**)&wkl, d_wkl);
    cudaGetSymbolAddress((void**)&wvh, d_wvh); cudaGetSymbolAddress((void**)&wvl, d_wvl);
    cudaGetSymbolAddress((void**)&woh, d_woh); cudaGetSymbolAddress((void**)&wol, d_wol);
    cudaGetSymbolAddress((void**)&w1h, d_w1h); cudaGetSymbolAddress((void**)&w1l, d_w1l);
    cudaGetSymbolAddress((void**)&w2h, d_w2h); cudaGetSymbolAddress((void**)&w2l, d_w2l);
    cudaGetSymbolAddress((void**)&w3h, d_w3h); cudaGetSymbolAddress((void**)&w3l, d_w3l);
    cudaGetSymbolAddress((void**)&lmh, d_lmh); cudaGetSymbolAddress((void**)&lml, d_lml);

    const int  BT = B_SZ * T_SZ;
    const long DD = (long)D_SZ * D_SZ;
    const long DF = (long)D_SZ * FF_SZ;

    // weight splits (graph-replayed each iteration; cheap vs GEMM savings)
    split(wq, wqh, wql, (long)L_SZ * DD);
    split(wk, wkh, wkl, (long)L_SZ * DD);
    split(wv, wvh, wvl, (long)L_SZ * DD);
    split(wo, woh, wol, (long)L_SZ * DD);
    split(w1, w1h, w1l, (long)L_SZ * DF);
    split(w2, w2h, w2l, (long)L_SZ * DF);
    split(w3, w3h, w3l, (long)L_SZ * DF);
    split(lm_head, lmh, lml, (long)D_SZ * V_SZ);

    // 1) embedding
    embed_kernel<<<(B_SZ * T_SZ * D_SZ) / 256, 256>>>(ids, emb, x);
    split(x, xh, xl, (long)BT * D_SZ);

    // 2) low-pass quality -> block selection
    dirichlet_kernel<<<T_SZ / 256, 256>>>(gk);
    buildG_kernel<<<(T_SZ * T_SZ) / 256, 256>>>(gk, G);
    split(G, Gh, Gl, (long)T_SZ * T_SZ);
    gemm_kn(Gh, Gl, xh, xl, h, T_SZ, D_SZ, T_SZ, T_SZ, D_SZ, D_SZ,
            0, (long)T_SZ * D_SZ, (long)T_SZ * D_SZ, 0, 0, 0, 1, B_SZ, 0);
    rho_kernel<<<BT, 256>>>(h, x, rho);
    select_blocks<<<1, 64>>>(rho, sel);

    // 3) transformer layers
    for (int l = 0; l < L_SZ; l++) {
        rmsnorm_split_kernel<<<BT, 256>>>(x, attn_norm + (size_t)l * D_SZ, (u32*)hh, (u32*)hl);

        gemm_kn(hh, hl, wqh + l * DD, wql + l * DD, q, BT, D_SZ, D_SZ, D_SZ, D_SZ, D_SZ,
                0, 0, 0, 0, 0, 0, 1, 1, 0);
        gemm_kn(hh, hl, wkh + l * DD, wkl + l * DD, k, BT, D_SZ, D_SZ, D_SZ, D_SZ, D_SZ,
                0, 0, 0, 0, 0, 0, 1, 1, 0);
        gemm_kn(hh, hl, wvh + l * DD, wvl + l * DD, v, BT, D_SZ, D_SZ, D_SZ, D_SZ, D_SZ,
                0, 0, 0, 0, 0, 0, 1, 1, 0);

        rope_kernel<<<(B_SZ * T_SZ * H_SZ * 32) / 256, 256>>>(q, k);
        split(q, qh, ql, (long)BT * D_SZ);
        split(k, kh, kl, (long)BT * D_SZ);
        split(v, vh, vl, (long)BT * D_SZ);

        // scores[b,h] = q_head @ k_head^T : B = k rows (NK layout)
        gemm_nk(qh, ql, kh, kl, sc, T_SZ, T_SZ, DH_SZ, D_SZ, D_SZ, T_SZ,
                (long)T_SZ * D_SZ, (long)T_SZ * D_SZ, (long)H_SZ * T_SZ * T_SZ,
                DH_SZ, DH_SZ, (long)T_SZ * T_SZ, H_SZ, B_SZ * H_SZ, 0);

        masked_softmax_kernel<<<B_SZ * H_SZ * T_SZ, 256>>>(sc, sel);
        split(sc, sch, scl, (long)B_SZ * H_SZ * T_SZ * T_SZ);

        // o_head = attn @ v_head (v natural KN layout)
        gemm_kn(sch, scl, vh, vl, o, T_SZ, DH_SZ, T_SZ, T_SZ, D_SZ, D_SZ,
                (long)H_SZ * T_SZ * T_SZ, (long)T_SZ * D_SZ, (long)T_SZ * D_SZ,
                (long)T_SZ * T_SZ, DH_SZ, DH_SZ, H_SZ, B_SZ * H_SZ, 0);

        split(o, oh, ol, (long)BT * D_SZ);
        gemm_kn(oh, ol, woh + l * DD, wol + l * DD, x, BT, D_SZ, D_SZ, D_SZ, D_SZ, D_SZ,
                0, 0, 0, 0, 0, 0, 1, 1, 1);

        // FFN
        rmsnorm_split_kernel<<<BT, 256>>>(x, ffn_norm + (size_t)l * D_SZ, (u32*)hh, (u32*)hl);
        gemm_kn(hh, hl, w1h + l * DF, w1l + l * DF, f1, BT, FF_SZ, D_SZ, D_SZ, FF_SZ, FF_SZ,
                0, 0, 0, 0, 0, 0, 1, 1, 0);
        gemm_kn(hh, hl, w3h + l * DF, w3l + l * DF, f3, BT, FF_SZ, D_SZ, D_SZ, FF_SZ, FF_SZ,
                0, 0, 0, 0, 0, 0, 1, 1, 0);
        silu_mul_kernel<<<(BT * FF_SZ) / 256, 256>>>(f1, f3);
        split(f1, f1h, f1l, (long)BT * FF_SZ);
        gemm_kn(f1h, f1l, w2h + l * DF, w2l + l * DF, x, BT, D_SZ, FF_SZ, FF_SZ, D_SZ, D_SZ,
                0, 0, 0, 0, 0, 0, 1, 1, 1);
    }

    // 4) final norm + lm_head
    rmsnorm_split_kernel<<<BT, 256>>>(x, final_norm, (u32*)hh, (u32*)hl);
    gemm_kn(hh, hl, lmh, lml, out, BT, V_SZ, D_SZ, D_SZ, V_SZ, V_SZ,
            0, 0, 0, 0, 0, 0, 1, 1, 0);
}

// round 7
// speedup vs baseline: 2.0970x; 1.0748x over previous
#include <cuda_runtime.h>
#include <math.h>

typedef unsigned short u16;
typedef unsigned int   u32;

// ---------------- problem constants ----------------
#define B_SZ 2
#define T_SZ 1024
#define D_SZ 1024
#define H_SZ 16
#define DH_SZ 64
#define FF_SZ 4096
#define L_SZ 2
#define V_SZ 32000
#define M_BLK 32
#define BS_SZ 32
#define TOPK 8
#define KEEP 128
#define EPSF 1e-6f
#define PI_D 3.14159265358979323846

// ---------------- fp32 scratch ----------------
__device__ float d_x [B_SZ*T_SZ*D_SZ];
__device__ float d_h [B_SZ*T_SZ*D_SZ];
__device__ float d_q [B_SZ*T_SZ*D_SZ];
__device__ float d_k [B_SZ*T_SZ*D_SZ];
__device__ float d_v [B_SZ*T_SZ*D_SZ];
__device__ float d_o [B_SZ*T_SZ*D_SZ];
__device__ float d_sc[(size_t)B_SZ*H_SZ*T_SZ*T_SZ];
__device__ float d_f1[B_SZ*T_SZ*FF_SZ];
__device__ float d_f3[B_SZ*T_SZ*FF_SZ];
__device__ float d_G [T_SZ*T_SZ];
__device__ float d_gk[T_SZ];
__device__ float d_rho[B_SZ*T_SZ];
__device__ int   d_sel[B_SZ*M_BLK];

// ---------------- bf16 hi/lo split planes ----------------
__device__ u16 d_xh [B_SZ*T_SZ*D_SZ],  d_xl [B_SZ*T_SZ*D_SZ];
__device__ u16 d_Gh [T_SZ*T_SZ],       d_Gl [T_SZ*T_SZ];
__device__ u16 d_hh [B_SZ*T_SZ*D_SZ],  d_hl [B_SZ*T_SZ*D_SZ];
__device__ u16 d_qh [B_SZ*T_SZ*D_SZ],  d_ql [B_SZ*T_SZ*D_SZ];
__device__ u16 d_kh [B_SZ*T_SZ*D_SZ],  d_kl [B_SZ*T_SZ*D_SZ];
__device__ u16 d_vh [B_SZ*T_SZ*D_SZ],  d_vl [B_SZ*T_SZ*D_SZ];
__device__ u16 d_sch[(size_t)B_SZ*H_SZ*T_SZ*T_SZ], d_scl[(size_t)B_SZ*H_SZ*T_SZ*T_SZ];
__device__ u16 d_oh [B_SZ*T_SZ*D_SZ],  d_ol [B_SZ*T_SZ*D_SZ];
__device__ u16 d_f1h[B_SZ*T_SZ*FF_SZ], d_f1l[B_SZ*T_SZ*FF_SZ];
__device__ u16 d_wqh[L_SZ*D_SZ*D_SZ],  d_wql[L_SZ*D_SZ*D_SZ];
__device__ u16 d_wkh[L_SZ*D_SZ*D_SZ],  d_wkl[L_SZ*D_SZ*D_SZ];
__device__ u16 d_wvh[L_SZ*D_SZ*D_SZ],  d_wvl[L_SZ*D_SZ*D_SZ];
__device__ u16 d_woh[L_SZ*D_SZ*D_SZ],  d_wol[L_SZ*D_SZ*D_SZ];
__device__ u16 d_w1h[L_SZ*D_SZ*FF_SZ], d_w1l[L_SZ*D_SZ*FF_SZ];
__device__ u16 d_w2h[L_SZ*FF_SZ*D_SZ], d_w2l[L_SZ*FF_SZ*D_SZ];
__device__ u16 d_w3h[L_SZ*D_SZ*FF_SZ], d_w3l[L_SZ*D_SZ*FF_SZ];
__device__ u16 d_lmh[(size_t)D_SZ*V_SZ], d_lml[(size_t)D_SZ*V_SZ];

// ---------------- split helpers ----------------
__device__ __forceinline__ void split2(float v0, float v1, u32 &hi, u32 &lo)
{
    asm("cvt.rn.bf16x2.f32 %0, %1, %2;" : "=r"(hi) : "f"(v1), "f"(v0));
    float h0 = __int_as_float(hi << 16);
    float h1 = __int_as_float(hi & 0xffff0000u);
    asm("cvt.rn.bf16x2.f32 %0, %1, %2;" : "=r"(lo) : "f"(v1 - h1), "f"(v0 - h0));
}

// vectorized split: n4 = n/4 float4 chunks
__global__ __launch_bounds__(256) void split_kernel(const float* __restrict__ in,
                                                    uint2* __restrict__ hi, uint2* __restrict__ lo,
                                                    long n4)
{
    long idx = (long)blockIdx.x * blockDim.x + threadIdx.x;
    if (idx >= n4) return;
    float4 v = reinterpret_cast<const float4*>(in)[idx];
    u32 h0, l0, h1, l1;
    split2(v.x, v.y, h0, l0);
    split2(v.z, v.w, h1, l1);
    hi[idx] = make_uint2(h0, h1);
    lo[idx] = make_uint2(l0, l1);
}

#define MMA_BF16(ACC, A, B0, B1)                                                 \
    asm volatile(                                                                \
        "mma.sync.aligned.m16n8k16.row.col.f32.bf16.bf16.f32 "                   \
        "{%0,%1,%2,%3}, {%4,%5,%6,%7}, {%8,%9}, {%0,%1,%2,%3};"                  \
        : "+f"(ACC[0]), "+f"(ACC[1]), "+f"(ACC[2]), "+f"(ACC[3])                 \
        : "r"(A[0]), "r"(A[1]), "r"(A[2]), "r"(A[3]), "r"(B0), "r"(B1))

#define LDSM4(R, ADDR)                                                           \
    asm volatile("ldmatrix.sync.aligned.m8n8.x4.shared.b16 {%0,%1,%2,%3},[%4];"  \
        : "=r"(R[0]), "=r"(R[1]), "=r"(R[2]), "=r"(R[3]) : "r"(ADDR))

#define LDSM4T(R0, R1, R2, R3, ADDR)                                             \
    asm volatile("ldmatrix.sync.aligned.m8n8.x4.trans.shared.b16 {%0,%1,%2,%3},[%4];" \
        : "=r"(R0), "=r"(R1), "=r"(R2), "=r"(R3) : "r"(ADDR))

// =====================================================================
// bf16 hi/lo 3-term GEMM with optional block-sparse attention modes.
// smode 0: dense.  smode 1: scores — early-exit output tiles whose
// (qblock, kvblock) pairs are all masked.  smode 2: attn@V — iterate only
// needed 32-wide K blocks (selected OR own-block of this 128-row q tile).
// Optional Chp/Clp: epilogue also emits bf16 hi/lo planes of C (beta=0 only).
// =====================================================================
#define LDA_S 40   // u16 stride (80B)

template<int BN, int WM, int WN, bool BNK>
__global__ __launch_bounds__(256, (BN == 64) ? 2 : 1)
void bf16_gemm_kernel(const u16* __restrict__ Ahi, const u16* __restrict__ Alo,
                      const u16* __restrict__ Bhi, const u16* __restrict__ Blo,
                      float* __restrict__ Cg,
                      int K, int lda, int ldb, int ldc,
                      long sAb, long sBb, long sCb, long sAh, long sBh, long sCh,
                      int Hdim, int beta,
                      const int* __restrict__ selp, int smode,
                      u32* __restrict__ Chp, u32* __restrict__ Clp)
{
    constexpr int BM = 128, BK = 32;
    constexpr int AM = BM / WM / 16;
    constexpr int AN = BN / WN / 8;
    constexpr int LDB_S = BNK ? LDA_S : (BN + 8);
    constexpr int A_PL  = BM * LDA_S;
    constexpr int B_PL  = BNK ? (BN * LDA_S) : (BK * LDB_S);
    constexpr int STAGE = 2 * A_PL + 2 * B_PL;

    extern __shared__ u16 sm[];
    __shared__ int klist[129];
    __shared__ int kcnt;

    int z = blockIdx.z, zb = z / Hdim, zh = z % Hdim;
    const int tid  = threadIdx.x, lane = tid & 31, w = tid >> 5;
    const int row0 = blockIdx.y * BM, col0 = blockIdx.x * BN;

    if (smode == 1) {
        // scores: skip output tile if no kv block is live for this q tile
        int qbmin = row0 >> 5, qbmax = qbmin + 3;
        bool need = false;
#pragma unroll
        for (int i = 0; i < BN / 32; i++) {
            int kb = (col0 >> 5) + i;
            if (kb <= qbmax && (selp[zb * M_BLK + kb] || kb >= qbmin)) need = true;
        }
        if (!need) return;
    }

    if (tid == 0) {
        int c = 0;
        if (smode == 2) {
            int qbmin = row0 >> 5, qbmax = qbmin + 3;
            for (int kb = 0; kb < K / 32; kb++)
                if (kb <= qbmax && (selp[zb * M_BLK + kb] || kb >= qbmin))
                    klist[c++] = kb * 32;
        } else {
            for (int t = 0; t < K / BK; t++) klist[c++] = t * BK;
        }
        kcnt = c;
    }
    __syncthreads();
    const int ntiles = kcnt;

    const u16* Ah = Ahi + zb * sAb + zh * sAh;
    const u16* Al = Alo + zb * sAb + zh * sAh;
    const u16* Bh = Bhi + zb * sBb + zh * sBh;
    const u16* Bl = Blo + zb * sBb + zh * sBh;
    float*     C  = Cg  + zb * sCb + zh * sCh;
    u32* Ch = Chp ? Chp + (zb * sCb + zh * sCh) / 2 : (u32*)0;
    u32* Cl = Clp ? Clp + (zb * sCb + zh * sCh) / 2 : (u32*)0;

    const int wm = w % WM, wn = w / WM;
    const int mW = wm * (BM / WM), nW = wn * (BN / WN);

    float acc[AM][AN][4];
#pragma unroll
    for (int i = 0; i < AM; i++)
#pragma unroll
        for (int j = 0; j < AN; j++)
#pragma unroll
            for (int r = 0; r < 4; r++) acc[i][j][r] = 0.f;

    auto cpa = [&](u16* dst, const u16* src) {
        u32 d = (u32)__cvta_generic_to_shared(dst);
        asm volatile("cp.async.cg.shared.global [%0],[%1],16;\n" :: "r"(d), "l"(src));
    };

    auto load_tile = [&](int s, int kt) {
        u16* base = sm + s * STAGE;
#pragma unroll
        for (int i = 0; i < 2; i++) {
            int ch = tid + i * 256;
            int r = ch >> 2, c = ch & 3;
            size_t go = (size_t)(row0 + r) * lda + kt + c * 8;
            cpa(base + r * LDA_S + c * 8,        Ah + go);
            cpa(base + A_PL + r * LDA_S + c * 8, Al + go);
        }
        u16* bb = base + 2 * A_PL;
        if (BNK) {
            constexpr int CH = BN * 4;
#pragma unroll
            for (int i = 0; i < CH / 256; i++) {
                int ch = tid + i * 256;
                int r = ch >> 2, c = ch & 3;
                size_t go = (size_t)(col0 + r) * ldb + kt + c * 8;
                cpa(bb + r * LDA_S + c * 8,        Bh + go);
                cpa(bb + B_PL + r * LDA_S + c * 8, Bl + go);
            }
        } else {
            constexpr int CPR = BN / 8;
            constexpr int CH  = BK * CPR;
#pragma unroll
            for (int i = 0; i < CH / 256; i++) {
                int ch = tid + i * 256;
                int r = ch / CPR, c = ch % CPR;
                size_t go = (size_t)(kt + r) * ldb + col0 + c * 8;
                cpa(bb + r * LDB_S + c * 8,        Bh + go);
                cpa(bb + B_PL + r * LDB_S + c * 8, Bl + go);
            }
        }
    };

    load_tile(0, klist[0]);
    asm volatile("cp.async.commit_group;\n" ::: "memory");

    for (int t = 0; t < ntiles; t++) {
        int s = t & 1;
        if (t + 1 < ntiles) {
            load_tile(s ^ 1, klist[t + 1]);
            asm volatile("cp.async.commit_group;\n" ::: "memory");
            asm volatile("cp.async.wait_group 1;\n" ::: "memory");
        } else {
            asm volatile("cp.async.wait_group 0;\n" ::: "memory");
        }
        __syncthreads();

        const u16* sa = sm + s * STAGE;
        const u16* sb = sa + 2 * A_PL;

#pragma unroll
        for (int ks = 0; ks < 2; ks++) {
            u32 ah[AM][4], al[AM][4], bh[AN][2], bl[AN][2];

            int arow = ((lane >> 3) & 1) * 8 + (lane & 7);
            int acol = ks * 16 + (lane >> 4) * 8;
#pragma unroll
            for (int am = 0; am < AM; am++) {
                const u16* p = sa + (mW + am * 16 + arow) * LDA_S + acol;
                u32 addr = (u32)__cvta_generic_to_shared(p);
                LDSM4(ah[am], addr);
                LDSM4(al[am], addr + A_PL * 2);
            }
            if (BNK) {
                int brow = ((lane >> 4) & 1) * 8 + (lane & 7);
                int bcol = ks * 16 + ((lane >> 3) & 1) * 8;
#pragma unroll
                for (int a2 = 0; a2 < AN / 2; a2++) {
                    const u16* p = sb + (nW + a2 * 16 + brow) * LDA_S + bcol;
                    u32 addr = (u32)__cvta_generic_to_shared(p);
                    asm volatile("ldmatrix.sync.aligned.m8n8.x4.shared.b16 {%0,%1,%2,%3},[%4];"
                        : "=r"(bh[2*a2][0]), "=r"(bh[2*a2][1]),
                          "=r"(bh[2*a2+1][0]), "=r"(bh[2*a2+1][1]) : "r"(addr));
                    asm volatile("ldmatrix.sync.aligned.m8n8.x4.shared.b16 {%0,%1,%2,%3},[%4];"
                        : "=r"(bl[2*a2][0]), "=r"(bl[2*a2][1]),
                          "=r"(bl[2*a2+1][0]), "=r"(bl[2*a2+1][1]) : "r"(addr + B_PL * 2));
                }
            } else {
                int brow = ks * 16 + ((lane >> 3) & 1) * 8 + (lane & 7);
                int bcol = (lane >> 4) * 8;
#pragma unroll
                for (int a2 = 0; a2 < AN / 2; a2++) {
                    const u16* p = sb + brow * LDB_S + nW + a2 * 16 + bcol;
                    u32 addr = (u32)__cvta_generic_to_shared(p);
                    LDSM4T(bh[2*a2][0], bh[2*a2][1], bh[2*a2+1][0], bh[2*a2+1][1], addr);
                    LDSM4T(bl[2*a2][0], bl[2*a2][1], bl[2*a2+1][0], bl[2*a2+1][1],
                           addr + B_PL * 2);
                }
            }

#pragma unroll
            for (int am = 0; am < AM; am++)
#pragma unroll
                for (int an = 0; an < AN; an++) {
                    MMA_BF16(acc[am][an], ah[am], bh[an][0], bh[an][1]);
                    MMA_BF16(acc[am][an], ah[am], bl[an][0], bl[an][1]);
                    MMA_BF16(acc[am][an], al[am], bh[an][0], bh[an][1]);
                }
        }
        __syncthreads();
    }

    // ---- epilogue ----
#pragma unroll
    for (int am = 0; am < AM; am++)
#pragma unroll
        for (int an = 0; an < AN; an++) {
            int r = row0 + mW + am * 16 + (lane >> 2);
            int c = col0 + nW + an * 8 + (lane & 3) * 2;
            size_t i0 = (size_t)r * ldc + c;
            size_t i1 = (size_t)(r + 8) * ldc + c;
            float2 v0 = make_float2(acc[am][an][0], acc[am][an][1]);
            float2 v1 = make_float2(acc[am][an][2], acc[am][an][3]);
            if (beta) {
                float2 p0 = *reinterpret_cast<const float2*>(C + i0);
                float2 p1 = *reinterpret_cast<const float2*>(C + i1);
                v0.x += p0.x; v0.y += p0.y; v1.x += p1.x; v1.y += p1.y;
            }
            *reinterpret_cast<float2*>(C + i0) = v0;
            *reinterpret_cast<float2*>(C + i1) = v1;
            if (Ch) {
                u32 hh_, ll_;
                split2(v0.x, v0.y, hh_, ll_);
                Ch[i0 >> 1] = hh_; Cl[i0 >> 1] = ll_;
                split2(v1.x, v1.y, hh_, ll_);
                Ch[i1 >> 1] = hh_; Cl[i1 >> 1] = ll_;
            }
        }
}

// ---------------- elementwise kernels ----------------
__global__ void embed_kernel(const int* __restrict__ ids, const float* __restrict__ emb,
                             float* __restrict__ x)
{
    int idx = blockIdx.x * blockDim.x + threadIdx.x;
    int d = idx & (D_SZ - 1);
    int bt = idx >> 10;
    x[idx] = emb[(size_t)ids[bt] * D_SZ + d];
}

__global__ void dirichlet_kernel(float* __restrict__ g)
{
    int d = blockIdx.x * blockDim.x + threadIdx.x;
    if (d >= T_SZ) return;
    double s = 0.0;
    for (int k = 1; k < KEEP; k++)
        s += cos(2.0 * PI_D * (double)k * (double)d / (double)T_SZ);
    g[d] = (float)((1.0 + 2.0 * s) / (double)T_SZ);
}

__global__ void buildG_kernel(const float* __restrict__ g, float* __restrict__ G)
{
    int i = blockIdx.x * blockDim.x + threadIdx.x;
    int t = i >> 10, s = i & (T_SZ - 1);
    G[i] = g[(t - s) & (T_SZ - 1)];
}

__global__ __launch_bounds__(256) void rho_kernel(const float* __restrict__ hlp,
                                                  const float* __restrict__ x,
                                                  float* __restrict__ rho)
{
    size_t row = (size_t)blockIdx.x * D_SZ;
    int tid = threadIdx.x;
    float s1 = 0.f, s2 = 0.f;
#pragma unroll
    for (int i = 0; i < 4; i++) {
        float a = hlp[row + tid + i * 256];
        float b = x  [row + tid + i * 256];
        s1 += a * a; s2 += b * b;
    }
    for (int o = 16; o > 0; o >>= 1) {
        s1 += __shfl_xor_sync(0xffffffffu, s1, o);
        s2 += __shfl_xor_sync(0xffffffffu, s2, o);
    }
    __shared__ float r1[8], r2[8];
    if ((tid & 31) == 0) { r1[tid >> 5] = s1; r2[tid >> 5] = s2; }
    __syncthreads();
    if (tid == 0) {
        float t1 = 0.f, t2 = 0.f;
        for (int i = 0; i < 8; i++) { t1 += r1[i]; t2 += r2[i]; }
        rho[blockIdx.x] = t1 / (t2 + EPSF);
    }
}

__global__ void select_blocks(const float* __restrict__ rho, int* __restrict__ sel)
{
    __shared__ float bq[B_SZ][M_BLK];
    int tid = threadIdx.x;
    if (tid < B_SZ * M_BLK) {
        int b = tid >> 5, m = tid & 31;
        float s = 0.f;
        for (int i = 0; i < BS_SZ; i++) s += rho[b * T_SZ + m * BS_SZ + i];
        bq[b][m] = s * (1.f / BS_SZ);
        sel[tid] = 0;
    }
    __syncthreads();
    if (tid < B_SZ) {
        int b = tid;
        bool picked[M_BLK];
        for (int m = 0; m < M_BLK; m++) picked[m] = false;
        for (int it = 0; it < TOPK; it++) {
            int best = -1; float bv = -3.4e38f;
            for (int m = 0; m < M_BLK; m++)
                if (!picked[m] && bq[b][m] > bv) { bv = bq[b][m]; best = m; }
            picked[best] = true;
            sel[b * M_BLK + best] = 1;
        }
    }
}

__global__ __launch_bounds__(256) void rmsnorm_split_kernel(
    const float* __restrict__ x, const float* __restrict__ w,
    u32* __restrict__ yh, u32* __restrict__ yl)
{
    size_t row = (size_t)blockIdx.x * D_SZ;
    int tid = threadIdx.x;
    float4 v = reinterpret_cast<const float4*>(x + row)[tid];
    float s = v.x * v.x + v.y * v.y + v.z * v.z + v.w * v.w;
    for (int o = 16; o > 0; o >>= 1) s += __shfl_xor_sync(0xffffffffu, s, o);
    __shared__ float red[8];
    if ((tid & 31) == 0) red[tid >> 5] = s;
    __syncthreads();
    float tot = 0.f;
    for (int i = 0; i < 8; i++) tot += red[i];
    float r = rsqrtf(tot * (1.f / D_SZ) + EPSF);
    float4 wv = reinterpret_cast<const float4*>(w)[tid];
    u32 h0, l0, h1, l1;
    split2(v.x * r * wv.x, v.y * r * wv.y, h0, l0);
    split2(v.z * r * wv.z, v.w * r * wv.w, h1, l1);
    size_t c = row / 2 + tid * 2;
    yh[c] = h0; yh[c + 1] = h1;
    yl[c] = l0; yl[c + 1] = l1;
}

// RoPE fused with split: reads q,k fp32, writes bf16 hi/lo planes only.
// thread handles elements (2j2, 2j2+1) and (2j2+32, 2j2+33) of one (b,t,h).
__global__ void rope_split_kernel(const float* __restrict__ q, const float* __restrict__ k,
                                  u32* __restrict__ qh, u32* __restrict__ ql,
                                  u32* __restrict__ kh, u32* __restrict__ kl)
{
    int idx = blockIdx.x * blockDim.x + threadIdx.x;   // B*T*H*16
    int j2 = idx & 15;
    int h  = (idx >> 4) & (H_SZ - 1);
    int t  = (idx >> 8) & (T_SZ - 1);
    int b  = idx >> 18;
    int e0 = 2 * j2;
    float inv0 = (float)(1.0 / pow(10000.0, (double)(2 * e0)     / (double)DH_SZ));
    float inv1 = (float)(1.0 / pow(10000.0, (double)(2 * (e0+1)) / (double)DH_SZ));
    float c0 = cosf(t * inv0), s0 = sinf(t * inv0);
    float c1 = cosf(t * inv1), s1 = sinf(t * inv1);
    size_t base = ((size_t)(b * T_SZ + t)) * D_SZ + h * DH_SZ + e0;
    float2 qa = *reinterpret_cast<const float2*>(q + base);
    float2 qb = *reinterpret_cast<const float2*>(q + base + 32);
    float2 ka = *reinterpret_cast<const float2*>(k + base);
    float2 kb = *reinterpret_cast<const float2*>(k + base + 32);
    float q0 = qa.x * c0 - qb.x * s0, q1 = qa.y * c1 - qb.y * s1;
    float q2 = qb.x * c0 + qa.x * s0, q3 = qb.y * c1 + qa.y * s1;
    float k0 = ka.x * c0 - kb.x * s0, k1 = ka.y * c1 - kb.y * s1;
    float k2 = kb.x * c0 + ka.x * s0, k3 = kb.y * c1 + ka.y * s1;
    size_t p0 = base >> 1, p1 = (base + 32) >> 1;
    u32 hh_, ll_;
    split2(q0, q1, hh_, ll_); qh[p0] = hh_; ql[p0] = ll_;
    split2(q2, q3, hh_, ll_); qh[p1] = hh_; ql[p1] = ll_;
    split2(k0, k1, hh_, ll_); kh[p0] = hh_; kl[p0] = ll_;
    split2(k2, k3, hh_, ll_); kh[p1] = hh_; kl[p1] = ll_;
}

// Masked softmax fused with split; block-sparse loads and stores.
// Loads only blocks that can be nonzero; writes (prob hi/lo planes) every
// block the sparse attn@V GEMM will read for this row's 128-row q tile.
__global__ __launch_bounds__(256) void masked_softmax_split_kernel(
    const float* __restrict__ s, const int* __restrict__ sel,
    u32* __restrict__ ph, u32* __restrict__ pl)
{
    int gid = blockIdx.x;                  // bh*T + tq
    int tq = gid & (T_SZ - 1);
    int b  = gid / (H_SZ * T_SZ);
    size_t row = (size_t)gid * T_SZ;
    int tid = threadIdx.x;
    const float scale = 0.125f;
    int qblk  = tq >> 5;
    int qbmin = (tq >> 7) << 2;            // 128-row GEMM tile q-block range
    int qbmax = qbmin + 3;

    float v[4];
    bool wlive[2];
    float mx = -3.4e38f;
#pragma unroll
    for (int i = 0; i < 2; i++) {
        int p  = tid + i * 256;            // pair index (2 floats)
        int kb = p >> 4;
        bool blive = (kb <= qblk) && (sel[b * M_BLK + kb] || kb == qblk);
        wlive[i]   = (kb <= qbmax) && (sel[b * M_BLK + kb] || kb >= qbmin);
        float2 vv = make_float2(-1e9f, -1e9f);
        if (blive) vv = *reinterpret_cast<const float2*>(s + row + 2 * p);
        int e0 = 2 * p;
        bool a0 = blive && (e0     <= tq);
        bool a1 = blive && (e0 + 1 <= tq);
        v[2*i]   = a0 ? vv.x * scale : -1e9f;
        v[2*i+1] = a1 ? vv.y * scale : -1e9f;
        mx = fmaxf(mx, fmaxf(v[2*i], v[2*i+1]));
    }
    for (int o = 16; o > 0; o >>= 1) mx = fmaxf(mx, __shfl_xor_sync(0xffffffffu, mx, o));
    __shared__ float red[8];
    if ((tid & 31) == 0) red[tid >> 5] = mx;
    __syncthreads();
    float m = red[0];
    for (int i = 1; i < 8; i++) m = fmaxf(m, red[i]);
    __syncthreads();
    float sum = 0.f;
#pragma unroll
    for (int i = 0; i < 4; i++) { v[i] = expf(v[i] - m); sum += v[i]; }
    for (int o = 16; o > 0; o >>= 1) sum += __shfl_xor_sync(0xffffffffu, sum, o);
    if ((tid & 31) == 0) red[tid >> 5] = sum;
    __syncthreads();
    float tot = 0.f;
    for (int i = 0; i < 8; i++) tot += red[i];
    float inv = 1.f / tot;
    size_t prow = row >> 1;
#pragma unroll
    for (int i = 0; i < 2; i++) {
        if (!wlive[i]) continue;
        int p = tid + i * 256;
        u32 hh_, ll_;
        split2(v[2*i] * inv, v[2*i+1] * inv, hh_, ll_);
        ph[prow + p] = hh_; pl[prow + p] = ll_;
    }
}

// SiLU gate fused with split: planes(silu(f1) * f3)
__global__ __launch_bounds__(256) void silu_split_kernel(const float* __restrict__ f1,
                                                         const float* __restrict__ f3,
                                                         u32* __restrict__ gh, u32* __restrict__ gl,
                                                         long n2)
{
    long idx = (long)blockIdx.x * blockDim.x + threadIdx.x;
    if (idx >= n2) return;
    float2 a = reinterpret_cast<const float2*>(f1)[idx];
    float2 g = reinterpret_cast<const float2*>(f3)[idx];
    float y0 = a.x / (1.f + expf(-a.x)) * g.x;
    float y1 = a.y / (1.f + expf(-a.y)) * g.y;
    u32 h, l;
    split2(y0, y1, h, l);
    gh[idx] = h; gl[idx] = l;
}

// ---------------- host launchers ----------------
static const int SMEM_KN128 = (2*128*LDA_S + 2*32*(128+8)) * 2 * 2;
static const int SMEM_KN64  = (2*128*LDA_S + 2*32*(64+8))  * 2 * 2;
static const int SMEM_NK64  = (2*128*LDA_S + 2*64*LDA_S)   * 2 * 2;

static void gemm_kn(const u16* Ah, const u16* Al, const u16* Bh, const u16* Bl, float* C,
                    int M, int N, int K, int lda, int ldb, int ldc,
                    long sAb, long sBb, long sCb, long sAh, long sBh, long sCh,
                    int Hdim, int nb, int beta,
                    const int* sel = 0, int smode = 0, u16* Ch = 0, u16* Cl = 0)
{
    if (N % 128 == 0 && N >= 4096) {
        dim3 grid(N / 128, M / 128, nb);
        bf16_gemm_kernel<128, 2, 4, false><<<grid, 256, SMEM_KN128>>>(
            Ah, Al, Bh, Bl, C, K, lda, ldb, ldc, sAb, sBb, sCb, sAh, sBh, sCh, Hdim, beta,
            sel, smode, (u32*)Ch, (u32*)Cl);
    } else {
        dim3 grid(N / 64, M / 128, nb);
        bf16_gemm_kernel<64, 4, 2, false><<<grid, 256, SMEM_KN64>>>(
            Ah, Al, Bh, Bl, C, K, lda, ldb, ldc, sAb, sBb, sCb, sAh, sBh, sCh, Hdim, beta,
            sel, smode, (u32*)Ch, (u32*)Cl);
    }
}

static void gemm_nk(const u16* Ah, const u16* Al, const u16* Bh, const u16* Bl, float* C,
                    int M, int N, int K, int lda, int ldb, int ldc,
                    long sAb, long sBb, long sCb, long sAh, long sBh, long sCh,
                    int Hdim, int nb, int beta,
                    const int* sel = 0, int smode = 0)
{
    dim3 grid(N / 64, M / 128, nb);
    bf16_gemm_kernel<64, 4, 2, true><<<grid, 256, SMEM_NK64>>>(
        Ah, Al, Bh, Bl, C, K, lda, ldb, ldc, sAb, sBb, sCb, sAh, sBh, sCh, Hdim, beta,
        sel, smode, (u32*)0, (u32*)0);
}

static void split(const float* in, u16* hi, u16* lo, long n)
{
    long n4 = n / 4;
    split_kernel<<<(unsigned)((n4 + 255) / 256), 256>>>(in, (uint2*)hi, (uint2*)lo, n4);
}

extern "C" void kernel_launch(void* const* d_in, const int* in_sizes, int n_in,
                              void* d_out, int out_size)
{
    const int*   ids        = (const int*)  d_in[0];
    const float* emb        = (const float*)d_in[1];
    const float* wq         = (const float*)d_in[2];
    const float* wk         = (const float*)d_in[3];
    const float* wv         = (const float*)d_in[4];
    const float* wo         = (const float*)d_in[5];
    const float* w1         = (const float*)d_in[6];
    const float* w2         = (const float*)d_in[7];
    const float* w3         = (const float*)d_in[8];
    const float* attn_norm  = (const float*)d_in[9];
    const float* ffn_norm   = (const float*)d_in[10];
    const float* final_norm = (const float*)d_in[11];
    const float* lm_head    = (const float*)d_in[12];
    float* out = (float*)d_out;

    static bool attrs_set = false;
    if (!attrs_set) {
        cudaFuncSetAttribute(bf16_gemm_kernel<128, 2, 4, false>,
                             cudaFuncAttributeMaxDynamicSharedMemorySize, SMEM_KN128);
        cudaFuncSetAttribute(bf16_gemm_kernel<64, 4, 2, false>,
                             cudaFuncAttributeMaxDynamicSharedMemorySize, SMEM_KN64);
        cudaFuncSetAttribute(bf16_gemm_kernel<64, 4, 2, true>,
                             cudaFuncAttributeMaxDynamicSharedMemorySize, SMEM_NK64);
        attrs_set = true;
    }

    float *x, *h, *q, *k, *v, *o, *sc, *f1, *f3, *G, *gk, *rho;
    int* sel;
    cudaGetSymbolAddress((void**)&x,   d_x);
    cudaGetSymbolAddress((void**)&h,   d_h);
    cudaGetSymbolAddress((void**)&q,   d_q);
    cudaGetSymbolAddress((void**)&k,   d_k);
    cudaGetSymbolAddress((void**)&v,   d_v);
    cudaGetSymbolAddress((void**)&o,   d_o);
    cudaGetSymbolAddress((void**)&sc,  d_sc);
    cudaGetSymbolAddress((void**)&f1,  d_f1);
    cudaGetSymbolAddress((void**)&f3,  d_f3);
    cudaGetSymbolAddress((void**)&G,   d_G);
    cudaGetSymbolAddress((void**)&gk,  d_gk);
    cudaGetSymbolAddress((void**)&rho, d_rho);
    cudaGetSymbolAddress((void**)&sel, d_sel);

    u16 *xh,*xl,*Gh,*Gl,*hh,*hl,*qh,*ql,*kh,*kl,*vh,*vl,*sch,*scl,*oh,*ol,*f1h,*f1l;
    u16 *wqh,*wql,*wkh,*wkl,*wvh,*wvl,*woh,*wol,*w1h,*w1l,*w2h,*w2l,*w3h,*w3l,*lmh,*lml;
    cudaGetSymbolAddress((void**)&xh, d_xh);   cudaGetSymbolAddress((void**)&xl, d_xl);
    cudaGetSymbolAddress((void**)&Gh, d_Gh);   cudaGetSymbolAddress((void**)&Gl, d_Gl);
    cudaGetSymbolAddress((void**)&hh, d_hh);   cudaGetSymbolAddress((void**)&hl, d_hl);
    cudaGetSymbolAddress((void**)&qh, d_qh);   cudaGetSymbolAddress((void**)&ql, d_ql);
    cudaGetSymbolAddress((void**)&kh, d_kh);   cudaGetSymbolAddress((void**)&kl, d_kl);
    cudaGetSymbolAddress((void**)&vh, d_vh);   cudaGetSymbolAddress((void**)&vl, d_vl);
    cudaGetSymbolAddress((void**)&sch, d_sch); cudaGetSymbolAddress((void**)&scl, d_scl);
    cudaGetSymbolAddress((void**)&oh, d_oh);   cudaGetSymbolAddress((void**)&ol, d_ol);
    cudaGetSymbolAddress((void**)&f1h, d_f1h); cudaGetSymbolAddress((void**)&f1l, d_f1l);
    cudaGetSymbolAddress((void**)&wqh, d_wqh); cudaGetSymbolAddress((void**)&wql, d_wql);
    cudaGetSymbolAddress((void**)&wkh, d_wkh); cudaGetSymbolAddress((void**)&wkl, d_wkl);
    cudaGetSymbolAddress((void**)&wvh, d_wvh); cudaGetSymbolAddress((void**)&wvl, d_wvl);
    cudaGetSymbolAddress((void**)&woh, d_woh); cudaGetSymbolAddress((void**)&wol, d_wol);
    cudaGetSymbolAddress((void**)&w1h, d_w1h); cudaGetSymbolAddress((void**)&w1l, d_w1l);
    cudaGetSymbolAddress((void**)&w2h, d_w2h); cudaGetSymbolAddress((void**)&w2l, d_w2l);
    cudaGetSymbolAddress((void**)&w3h, d_w3h); cudaGetSymbolAddress((void**)&w3l, d_w3l);
    cudaGetSymbolAddress((void**)&lmh, d_lmh); cudaGetSymbolAddress((void**)&lml, d_lml);

    const int  BT = B_SZ * T_SZ;
    const long DD = (long)D_SZ * D_SZ;
    const long DF = (long)D_SZ * FF_SZ;

    // weight splits
    split(wq, wqh, wql, (long)L_SZ * DD);
    split(wk, wkh, wkl, (long)L_SZ * DD);
    split(wv, wvh, wvl, (long)L_SZ * DD);
    split(wo, woh, wol, (long)L_SZ * DD);
    split(w1, w1h, w1l, (long)L_SZ * DF);
    split(w2, w2h, w2l, (long)L_SZ * DF);
    split(w3, w3h, w3l, (long)L_SZ * DF);
    split(lm_head, lmh, lml, (long)D_SZ * V_SZ);

    // 1) embedding
    embed_kernel<<<(B_SZ * T_SZ * D_SZ) / 256, 256>>>(ids, emb, x);
    split(x, xh, xl, (long)BT * D_SZ);

    // 2) low-pass quality -> block selection
    dirichlet_kernel<<<T_SZ / 256, 256>>>(gk);
    buildG_kernel<<<(T_SZ * T_SZ) / 256, 256>>>(gk, G);
    split(G, Gh, Gl, (long)T_SZ * T_SZ);
    gemm_kn(Gh, Gl, xh, xl, h, T_SZ, D_SZ, T_SZ, T_SZ, D_SZ, D_SZ,
            0, (long)T_SZ * D_SZ, (long)T_SZ * D_SZ, 0, 0, 0, 1, B_SZ, 0);
    rho_kernel<<<BT, 256>>>(h, x, rho);
    select_blocks<<<1, 64>>>(rho, sel);

    // 3) transformer layers
    for (int l = 0; l < L_SZ; l++) {
        rmsnorm_split_kernel<<<BT, 256>>>(x, attn_norm + (size_t)l * D_SZ, (u32*)hh, (u32*)hl);

        gemm_kn(hh, hl, wqh + l * DD, wql + l * DD, q, BT, D_SZ, D_SZ, D_SZ, D_SZ, D_SZ,
                0, 0, 0, 0, 0, 0, 1, 1, 0);
        gemm_kn(hh, hl, wkh + l * DD, wkl + l * DD, k, BT, D_SZ, D_SZ, D_SZ, D_SZ, D_SZ,
                0, 0, 0, 0, 0, 0, 1, 1, 0);
        gemm_kn(hh, hl, wvh + l * DD, wvl + l * DD, v, BT, D_SZ, D_SZ, D_SZ, D_SZ, D_SZ,
                0, 0, 0, 0, 0, 0, 1, 1, 0, 0, 0, vh, vl);

        rope_split_kernel<<<(B_SZ * T_SZ * H_SZ * 16) / 256, 256>>>(
            q, k, (u32*)qh, (u32*)ql, (u32*)kh, (u32*)kl);

        // scores (sparse output tiles)
        gemm_nk(qh, ql, kh, kl, sc, T_SZ, T_SZ, DH_SZ, D_SZ, D_SZ, T_SZ,
                (long)T_SZ * D_SZ, (long)T_SZ * D_SZ, (long)H_SZ * T_SZ * T_SZ,
                DH_SZ, DH_SZ, (long)T_SZ * T_SZ, H_SZ, B_SZ * H_SZ, 0, sel, 1);

        masked_softmax_split_kernel<<<B_SZ * H_SZ * T_SZ, 256>>>(
            sc, sel, (u32*)sch, (u32*)scl);

        // o_head = attn @ v_head (sparse K blocks; emits o planes)
        gemm_kn(sch, scl, vh, vl, o, T_SZ, DH_SZ, T_SZ, T_SZ, D_SZ, D_SZ,
                (long)H_SZ * T_SZ * T_SZ, (long)T_SZ * D_SZ, (long)T_SZ * D_SZ,
                (long)T_SZ * T_SZ, DH_SZ, DH_SZ, H_SZ, B_SZ * H_SZ, 0, sel, 2, oh, ol);

        gemm_kn(oh, ol, woh + l * DD, wol + l * DD, x, BT, D_SZ, D_SZ, D_SZ, D_SZ, D_SZ,
                0, 0, 0, 0, 0, 0, 1, 1, 1);

        // FFN
        rmsnorm_split_kernel<<<BT, 256>>>(x, ffn_norm + (size_t)l * D_SZ, (u32*)hh, (u32*)hl);
        gemm_kn(hh, hl, w1h + l * DF, w1l + l * DF, f1, BT, FF_SZ, D_SZ, D_SZ, FF_SZ, FF_SZ,
                0, 0, 0, 0, 0, 0, 1, 1, 0);
        gemm_kn(hh, hl, w3h + l * DF, w3l + l * DF, f3, BT, FF_SZ, D_SZ, D_SZ, FF_SZ, FF_SZ,
                0, 0, 0, 0, 0, 0, 1, 1, 0);
        silu_split_kernel<<<(BT * FF_SZ / 2 + 255) / 256, 256>>>(
            f1, f3, (u32*)f1h, (u32*)f1l, (long)BT * FF_SZ / 2);
        gemm_kn(f1h, f1l, w2h + l * DF, w2l + l * DF, x, BT, D_SZ, FF_SZ, FF_SZ, D_SZ, D_SZ,
                0, 0, 0, 0, 0, 0, 1, 1, 1);
    }

    // 4) final norm + lm_head
    rmsnorm_split_kernel<<<BT, 256>>>(x, final_norm, (u32*)hh, (u32*)hl);
    gemm_kn(hh, hl, lmh, lml, out, BT, V_SZ, D_SZ, D_SZ, V_SZ, V_SZ,
            0, 0, 0, 0, 0, 0, 1, 1, 0);
}

// round 9
// speedup vs baseline: 2.1797x; 1.0394x over previous
#include <cuda_runtime.h>
#include <math.h>

typedef unsigned short u16;
typedef unsigned int   u32;

// ---------------- problem constants ----------------
#define B_SZ 2
#define T_SZ 1024
#define D_SZ 1024
#define H_SZ 16
#define DH_SZ 64
#define FF_SZ 4096
#define L_SZ 2
#define V_SZ 32000
#define M_BLK 32
#define BS_SZ 32
#define TOPK 8
#define KEEP 128
#define EPSF 1e-6f
#define PI_D 3.14159265358979323846

// ---------------- fp32 scratch ----------------
__device__ float d_x  [B_SZ*T_SZ*D_SZ];
__device__ float d_h  [B_SZ*T_SZ*D_SZ];
__device__ float d_qkv[3*B_SZ*T_SZ*D_SZ];            // contiguous q|k|v
__device__ float d_o  [B_SZ*T_SZ*D_SZ];
__device__ float d_sc [(size_t)B_SZ*H_SZ*T_SZ*T_SZ];
__device__ float d_f13[2*B_SZ*T_SZ*FF_SZ];           // contiguous f1|f3
__device__ float d_G  [T_SZ*T_SZ];
__device__ float d_gk [T_SZ];
__device__ float d_rho[B_SZ*T_SZ];
__device__ int   d_sel[B_SZ*M_BLK];

// ---------------- bf16 hi/lo planes ----------------
__device__ u16 d_xh  [B_SZ*T_SZ*D_SZ],   d_xl  [B_SZ*T_SZ*D_SZ];
__device__ u16 d_Gh  [T_SZ*T_SZ],        d_Gl  [T_SZ*T_SZ];
__device__ u16 d_hh  [B_SZ*T_SZ*D_SZ],   d_hl  [B_SZ*T_SZ*D_SZ];
__device__ u16 d_qkvh[3*B_SZ*T_SZ*D_SZ], d_qkvl[3*B_SZ*T_SZ*D_SZ];
__device__ u16 d_sch [(size_t)B_SZ*H_SZ*T_SZ*T_SZ], d_scl[(size_t)B_SZ*H_SZ*T_SZ*T_SZ];
__device__ u16 d_oh  [B_SZ*T_SZ*D_SZ],   d_ol  [B_SZ*T_SZ*D_SZ];
__device__ u16 d_f1h [B_SZ*T_SZ*FF_SZ],  d_f1l [B_SZ*T_SZ*FF_SZ];
// weights (natural [K][N] layout planes)
__device__ u16 d_wqkvh[L_SZ*3*D_SZ*D_SZ], d_wqkvl[L_SZ*3*D_SZ*D_SZ];
__device__ u16 d_woh [L_SZ*D_SZ*D_SZ],   d_wol [L_SZ*D_SZ*D_SZ];
__device__ u16 d_w13h[L_SZ*2*D_SZ*FF_SZ], d_w13l[L_SZ*2*D_SZ*FF_SZ];
__device__ u16 d_w2h [L_SZ*FF_SZ*D_SZ],  d_w2l [L_SZ*FF_SZ*D_SZ];
__device__ u16 d_lmh [(size_t)D_SZ*V_SZ], d_lml [(size_t)D_SZ*V_SZ];

// ---------------- split helpers ----------------
__device__ __forceinline__ void split2(float v0, float v1, u32 &hi, u32 &lo)
{
    asm("cvt.rn.bf16x2.f32 %0, %1, %2;" : "=r"(hi) : "f"(v1), "f"(v0));
    float h0 = __int_as_float(hi << 16);
    float h1 = __int_as_float(hi & 0xffff0000u);
    asm("cvt.rn.bf16x2.f32 %0, %1, %2;" : "=r"(lo) : "f"(v1 - h1), "f"(v0 - h0));
}

__global__ __launch_bounds__(256) void split_kernel(const float* __restrict__ in,
                                                    uint2* __restrict__ hi, uint2* __restrict__ lo,
                                                    long n4)
{
    long idx = (long)blockIdx.x * blockDim.x + threadIdx.x;
    if (idx >= n4) return;
    float4 v = reinterpret_cast<const float4*>(in)[idx];
    u32 h0, l0, h1, l1;
    split2(v.x, v.y, h0, l0);
    split2(v.z, v.w, h1, l1);
    hi[idx] = make_uint2(h0, h1);
    lo[idx] = make_uint2(l0, l1);
}

#define MMA_BF16(ACC, A, B0, B1)                                                 \
    asm volatile(                                                                \
        "mma.sync.aligned.m16n8k16.row.col.f32.bf16.bf16.f32 "                   \
        "{%0,%1,%2,%3}, {%4,%5,%6,%7}, {%8,%9}, {%0,%1,%2,%3};"                  \
        : "+f"(ACC[0]), "+f"(ACC[1]), "+f"(ACC[2]), "+f"(ACC[3])                 \
        : "r"(A[0]), "r"(A[1]), "r"(A[2]), "r"(A[3]), "r"(B0), "r"(B1))

#define LDSM4(R, ADDR)                                                           \
    asm volatile("ldmatrix.sync.aligned.m8n8.x4.shared.b16 {%0,%1,%2,%3},[%4];"  \
        : "=r"(R[0]), "=r"(R[1]), "=r"(R[2]), "=r"(R[3]) : "r"(ADDR))

#define LDSM4T(R0, R1, R2, R3, ADDR)                                             \
    asm volatile("ldmatrix.sync.aligned.m8n8.x4.trans.shared.b16 {%0,%1,%2,%3},[%4];" \
        : "=r"(R0), "=r"(R1), "=r"(R2), "=r"(R3) : "r"(ADDR))

// =====================================================================
// bf16 hi/lo 3-term GEMM with optional block-sparse attention modes.
// smode 0: dense. smode 1: scores (skip dead output tiles).
// smode 2: attn@V (iterate only live 32-wide K blocks).
// Optional Chp/Clp: epilogue also emits bf16 hi/lo planes (beta=0 only).
// BNK=true: B stored row-major [N][K] (logical B = that array transposed).
// =====================================================================
#define LDA_S 40   // u16 stride (80B)

template<bool BNK>
__global__ __launch_bounds__(256, 2)
void bf16_gemm_kernel(const u16* __restrict__ Ahi, const u16* __restrict__ Alo,
                      const u16* __restrict__ Bhi, const u16* __restrict__ Blo,
                      float* __restrict__ Cg,
                      int K, int lda, int ldb, int ldc,
                      long sAb, long sBb, long sCb, long sAh, long sBh, long sCh,
                      int Hdim, int beta,
                      const int* __restrict__ selp, int smode,
                      u32* __restrict__ Chp, u32* __restrict__ Clp)
{
    constexpr int BM = 128, BK = 32, BN = 64, WM = 4, WN = 2;
    constexpr int AM = 2, AN = 4;
    constexpr int LDB_S = BNK ? LDA_S : (BN + 8);
    constexpr int A_PL  = BM * LDA_S;
    constexpr int B_PL  = BNK ? (BN * LDA_S) : (BK * LDB_S);
    constexpr int STAGE = 2 * A_PL + 2 * B_PL;

    extern __shared__ u16 smu[];
    __shared__ int klist[129];
    __shared__ int kcnt;

    int z = blockIdx.z, zb = z / Hdim, zh = z % Hdim;
    const int tid = threadIdx.x, lane = tid & 31, w = tid >> 5;
    const int row0 = blockIdx.y * BM, col0 = blockIdx.x * BN;

    if (smode == 1) {
        int qbmin = row0 >> 5, qbmax = qbmin + 3;
        bool need = false;
#pragma unroll
        for (int i = 0; i < 2; i++) {
            int kb = (col0 >> 5) + i;
            if (kb <= qbmax && (selp[zb * M_BLK + kb] || kb >= qbmin)) need = true;
        }
        if (!need) return;
    }
    if (tid == 0) {
        int c = 0;
        if (smode == 2) {
            int qbmin = row0 >> 5, qbmax = qbmin + 3;
            for (int kb = 0; kb < K / 32; kb++)
                if (kb <= qbmax && (selp[zb * M_BLK + kb] || kb >= qbmin))
                    klist[c++] = kb * 32;
        } else {
            for (int t = 0; t < K / BK; t++) klist[c++] = t * BK;
        }
        kcnt = c;
    }
    __syncthreads();
    const int ntiles = kcnt;

    const u16* Ah = Ahi + zb * sAb + zh * sAh;
    const u16* Al = Alo + zb * sAb + zh * sAh;
    const u16* Bh = Bhi + zb * sBb + zh * sBh;
    const u16* Bl = Blo + zb * sBb + zh * sBh;
    float*     C  = Cg  + zb * sCb + zh * sCh;
    u32* Ch = Chp ? Chp + (zb * sCb + zh * sCh) / 2 : (u32*)0;
    u32* Cl = Clp ? Clp + (zb * sCb + zh * sCh) / 2 : (u32*)0;

    const int wm = w % WM, wn = w / WM;
    const int mW = wm * (BM / WM), nW = wn * (BN / WN);

    float acc[AM][AN][4];
#pragma unroll
    for (int i = 0; i < AM; i++)
#pragma unroll
        for (int j = 0; j < AN; j++)
#pragma unroll
            for (int r = 0; r < 4; r++) acc[i][j][r] = 0.f;

    auto cpa = [&](u16* dst, const u16* src) {
        u32 d = (u32)__cvta_generic_to_shared(dst);
        asm volatile("cp.async.cg.shared.global [%0],[%1],16;\n" :: "r"(d), "l"(src));
    };
    auto load_tile = [&](int s, int kt) {
        u16* base = smu + s * STAGE;
#pragma unroll
        for (int i = 0; i < 2; i++) {
            int ch = tid + i * 256;
            int r = ch >> 2, c = ch & 3;
            size_t go = (size_t)(row0 + r) * lda + kt + c * 8;
            cpa(base + r * LDA_S + c * 8,        Ah + go);
            cpa(base + A_PL + r * LDA_S + c * 8, Al + go);
        }
        u16* bb = base + 2 * A_PL;
        if (BNK) {
            int r = tid >> 2, c = tid & 3;
            size_t go = (size_t)(col0 + r) * ldb + kt + c * 8;
            cpa(bb + r * LDA_S + c * 8,        Bh + go);
            cpa(bb + B_PL + r * LDA_S + c * 8, Bl + go);
        } else {
            int r = tid >> 3, c = tid & 7;
            size_t go = (size_t)(kt + r) * ldb + col0 + c * 8;
            cpa(bb + r * LDB_S + c * 8,        Bh + go);
            cpa(bb + B_PL + r * LDB_S + c * 8, Bl + go);
        }
    };

    load_tile(0, klist[0]);
    asm volatile("cp.async.commit_group;\n" ::: "memory");

    for (int t = 0; t < ntiles; t++) {
        int s = t & 1;
        if (t + 1 < ntiles) {
            load_tile(s ^ 1, klist[t + 1]);
            asm volatile("cp.async.commit_group;\n" ::: "memory");
            asm volatile("cp.async.wait_group 1;\n" ::: "memory");
        } else {
            asm volatile("cp.async.wait_group 0;\n" ::: "memory");
        }
        __syncthreads();
        const u16* sa = smu + s * STAGE;
        const u16* sb = sa + 2 * A_PL;
#pragma unroll
        for (int ks = 0; ks < 2; ks++) {
            u32 ah[AM][4], al[AM][4], bh[AN][2], bl[AN][2];
            int arow = ((lane >> 3) & 1) * 8 + (lane & 7);
            int acol = ks * 16 + (lane >> 4) * 8;
#pragma unroll
            for (int am = 0; am < AM; am++) {
                const u16* p = sa + (mW + am * 16 + arow) * LDA_S + acol;
                u32 addr = (u32)__cvta_generic_to_shared(p);
                LDSM4(ah[am], addr);
                LDSM4(al[am], addr + A_PL * 2);
            }
            if (BNK) {
                int brow = ((lane >> 4) & 1) * 8 + (lane & 7);
                int bcol = ks * 16 + ((lane >> 3) & 1) * 8;
#pragma unroll
                for (int a2 = 0; a2 < AN / 2; a2++) {
                    const u16* p = sb + (nW + a2 * 16 + brow) * LDA_S + bcol;
                    u32 addr = (u32)__cvta_generic_to_shared(p);
                    asm volatile("ldmatrix.sync.aligned.m8n8.x4.shared.b16 {%0,%1,%2,%3},[%4];"
                        : "=r"(bh[2*a2][0]), "=r"(bh[2*a2][1]),
                          "=r"(bh[2*a2+1][0]), "=r"(bh[2*a2+1][1]) : "r"(addr));
                    asm volatile("ldmatrix.sync.aligned.m8n8.x4.shared.b16 {%0,%1,%2,%3},[%4];"
                        : "=r"(bl[2*a2][0]), "=r"(bl[2*a2][1]),
                          "=r"(bl[2*a2+1][0]), "=r"(bl[2*a2+1][1]) : "r"(addr + B_PL * 2));
                }
            } else {
                int brow = ks * 16 + ((lane >> 3) & 1) * 8 + (lane & 7);
                int bcol = (lane >> 4) * 8;
#pragma unroll
                for (int a2 = 0; a2 < AN / 2; a2++) {
                    const u16* p = sb + brow * LDB_S + nW + a2 * 16 + bcol;
                    u32 addr = (u32)__cvta_generic_to_shared(p);
                    LDSM4T(bh[2*a2][0], bh[2*a2][1], bh[2*a2+1][0], bh[2*a2+1][1], addr);
                    LDSM4T(bl[2*a2][0], bl[2*a2][1], bl[2*a2+1][0], bl[2*a2+1][1],
                           addr + B_PL * 2);
                }
            }
#pragma unroll
            for (int am = 0; am < AM; am++)
#pragma unroll
                for (int an = 0; an < AN; an++) {
                    MMA_BF16(acc[am][an], ah[am], bh[an][0], bh[an][1]);
                    MMA_BF16(acc[am][an], ah[am], bl[an][0], bl[an][1]);
                    MMA_BF16(acc[am][an], al[am], bh[an][0], bh[an][1]);
                }
        }
        __syncthreads();
    }

#pragma unroll
    for (int am = 0; am < AM; am++)
#pragma unroll
        for (int an = 0; an < AN; an++) {
            int r = row0 + mW + am * 16 + (lane >> 2);
            int c = col0 + nW + an * 8 + (lane & 3) * 2;
            size_t i0 = (size_t)r * ldc + c;
            size_t i1 = (size_t)(r + 8) * ldc + c;
            float2 v0 = make_float2(acc[am][an][0], acc[am][an][1]);
            float2 v1 = make_float2(acc[am][an][2], acc[am][an][3]);
            if (beta) {
                float2 p0 = *reinterpret_cast<const float2*>(C + i0);
                float2 p1 = *reinterpret_cast<const float2*>(C + i1);
                v0.x += p0.x; v0.y += p0.y; v1.x += p1.x; v1.y += p1.y;
            }
            *reinterpret_cast<float2*>(C + i0) = v0;
            *reinterpret_cast<float2*>(C + i1) = v1;
            if (Ch) {
                u32 hh_, ll_;
                split2(v0.x, v0.y, hh_, ll_);
                Ch[i0 >> 1] = hh_; Cl[i0 >> 1] = ll_;
                split2(v1.x, v1.y, hh_, ll_);
                Ch[i1 >> 1] = hh_; Cl[i1 >> 1] = ll_;
            }
        }
}

// ---------------- elementwise kernels ----------------
// embedding gather fused with split
__global__ void embed_split_kernel(const int* __restrict__ ids, const float* __restrict__ emb,
                                   float* __restrict__ x, u32* __restrict__ xh, u32* __restrict__ xl)
{
    int idx = blockIdx.x * blockDim.x + threadIdx.x;   // B*T*D/2
    int d2 = idx & 511;
    int bt = idx >> 9;
    float2 v = *reinterpret_cast<const float2*>(emb + (size_t)ids[bt] * D_SZ + d2 * 2);
    *reinterpret_cast<float2*>(x + (size_t)bt * D_SZ + d2 * 2) = v;
    u32 h, l;
    split2(v.x, v.y, h, l);
    xh[idx] = h; xl[idx] = l;
}

__global__ void dirichlet_kernel(float* __restrict__ g)
{
    int d = blockIdx.x * blockDim.x + threadIdx.x;
    if (d >= T_SZ) return;
    double s = 0.0;
    for (int k = 1; k < KEEP; k++)
        s += cos(2.0 * PI_D * (double)k * (double)d / (double)T_SZ);
    g[d] = (float)((1.0 + 2.0 * s) / (double)T_SZ);
}

__global__ void buildG_kernel(const float* __restrict__ g, float* __restrict__ G)
{
    int i = blockIdx.x * blockDim.x + threadIdx.x;
    int t = i >> 10, s = i & (T_SZ - 1);
    G[i] = g[(t - s) & (T_SZ - 1)];
}

__global__ __launch_bounds__(256) void rho_kernel(const float* __restrict__ hlp,
                                                  const float* __restrict__ x,
                                                  float* __restrict__ rho)
{
    size_t row = (size_t)blockIdx.x * D_SZ;
    int tid = threadIdx.x;
    float s1 = 0.f, s2 = 0.f;
#pragma unroll
    for (int i = 0; i < 4; i++) {
        float a = hlp[row + tid + i * 256];
        float b = x  [row + tid + i * 256];
        s1 += a * a; s2 += b * b;
    }
    for (int o = 16; o > 0; o >>= 1) {
        s1 += __shfl_xor_sync(0xffffffffu, s1, o);
        s2 += __shfl_xor_sync(0xffffffffu, s2, o);
    }
    __shared__ float r1[8], r2[8];
    if ((tid & 31) == 0) { r1[tid >> 5] = s1; r2[tid >> 5] = s2; }
    __syncthreads();
    if (tid == 0) {
        float t1 = 0.f, t2 = 0.f;
        for (int i = 0; i < 8; i++) { t1 += r1[i]; t2 += r2[i]; }
        rho[blockIdx.x] = t1 / (t2 + EPSF);
    }
}

__global__ void select_blocks(const float* __restrict__ rho, int* __restrict__ sel)
{
    __shared__ float bq[B_SZ][M_BLK];
    int tid = threadIdx.x;
    if (tid < B_SZ * M_BLK) {
        int b = tid >> 5, m = tid & 31;
        float s = 0.f;
        for (int i = 0; i < BS_SZ; i++) s += rho[b * T_SZ + m * BS_SZ + i];
        bq[b][m] = s * (1.f / BS_SZ);
        sel[tid] = 0;
    }
    __syncthreads();
    if (tid < B_SZ) {
        int b = tid;
        bool picked[M_BLK];
        for (int m = 0; m < M_BLK; m++) picked[m] = false;
        for (int it = 0; it < TOPK; it++) {
            int best = -1; float bv = -3.4e38f;
            for (int m = 0; m < M_BLK; m++)
                if (!picked[m] && bq[b][m] > bv) { bv = bq[b][m]; best = m; }
            picked[best] = true;
            sel[b * M_BLK + best] = 1;
        }
    }
}

__global__ __launch_bounds__(256) void rmsnorm_split_kernel(
    const float* __restrict__ x, const float* __restrict__ w,
    u32* __restrict__ yh, u32* __restrict__ yl)
{
    size_t row = (size_t)blockIdx.x * D_SZ;
    int tid = threadIdx.x;
    float4 v = reinterpret_cast<const float4*>(x + row)[tid];
    float s = v.x * v.x + v.y * v.y + v.z * v.z + v.w * v.w;
    for (int o = 16; o > 0; o >>= 1) s += __shfl_xor_sync(0xffffffffu, s, o);
    __shared__ float red[8];
    if ((tid & 31) == 0) red[tid >> 5] = s;
    __syncthreads();
    float tot = 0.f;
    for (int i = 0; i < 8; i++) tot += red[i];
    float r = rsqrtf(tot * (1.f / D_SZ) + EPSF);
    float4 wv = reinterpret_cast<const float4*>(w)[tid];
    u32 h0, l0, h1, l1;
    split2(v.x * r * wv.x, v.y * r * wv.y, h0, l0);
    split2(v.z * r * wv.z, v.w * r * wv.w, h1, l1);
    size_t c = row / 2 + tid * 2;
    yh[c] = h0; yh[c + 1] = h1;
    yl[c] = l0; yl[c + 1] = l1;
}

// RoPE fused with split: reads q,k fp32 from contiguous qkv, writes planes.
__global__ void rope_split_kernel(const float* __restrict__ qkv,
                                  u32* __restrict__ qkvh, u32* __restrict__ qkvl)
{
    const int QK = B_SZ * T_SZ * D_SZ;
    int idx = blockIdx.x * blockDim.x + threadIdx.x;   // B*T*H*16
    int j2 = idx & 15;
    int h  = (idx >> 4) & (H_SZ - 1);
    int t  = (idx >> 8) & (T_SZ - 1);
    int b  = idx >> 18;
    int e0 = 2 * j2;
    float inv0 = (float)(1.0 / pow(10000.0, (double)(2 * e0)     / (double)DH_SZ));
    float inv1 = (float)(1.0 / pow(10000.0, (double)(2 * (e0+1)) / (double)DH_SZ));
    float c0 = cosf(t * inv0), s0 = sinf(t * inv0);
    float c1 = cosf(t * inv1), s1 = sinf(t * inv1);
    size_t base = ((size_t)(b * T_SZ + t)) * D_SZ + h * DH_SZ + e0;
    float2 qa = *reinterpret_cast<const float2*>(qkv + base);
    float2 qb = *reinterpret_cast<const float2*>(qkv + base + 32);
    float2 ka = *reinterpret_cast<const float2*>(qkv + QK + base);
    float2 kb = *reinterpret_cast<const float2*>(qkv + QK + base + 32);
    float q0 = qa.x * c0 - qb.x * s0, q1 = qa.y * c1 - qb.y * s1;
    float q2 = qb.x * c0 + qa.x * s0, q3 = qb.y * c1 + qa.y * s1;
    float k0 = ka.x * c0 - kb.x * s0, k1 = ka.y * c1 - kb.y * s1;
    float k2 = kb.x * c0 + ka.x * s0, k3 = kb.y * c1 + ka.y * s1;
    size_t p0 = base >> 1, p1 = (base + 32) >> 1;
    const size_t QK2 = QK / 2;
    u32 hh_, ll_;
    split2(q0, q1, hh_, ll_); qkvh[p0] = hh_;       qkvl[p0] = ll_;
    split2(q2, q3, hh_, ll_); qkvh[p1] = hh_;       qkvl[p1] = ll_;
    split2(k0, k1, hh_, ll_); qkvh[QK2 + p0] = hh_; qkvl[QK2 + p0] = ll_;
    split2(k2, k3, hh_, ll_); qkvh[QK2 + p1] = hh_; qkvl[QK2 + p1] = ll_;
}

__global__ __launch_bounds__(256) void masked_softmax_split_kernel(
    const float* __restrict__ s, const int* __restrict__ sel,
    u32* __restrict__ ph, u32* __restrict__ pl)
{
    int gid = blockIdx.x;
    int tq = gid & (T_SZ - 1);
    int b  = gid / (H_SZ * T_SZ);
    size_t row = (size_t)gid * T_SZ;
    int tid = threadIdx.x;
    const float scale = 0.125f;
    int qblk  = tq >> 5;
    int qbmin = (tq >> 7) << 2;
    int qbmax = qbmin + 3;

    float v[4];
    bool wlive[2];
    float mx = -3.4e38f;
#pragma unroll
    for (int i = 0; i < 2; i++) {
        int p  = tid + i * 256;
        int kb = p >> 4;
        bool blive = (kb <= qblk) && (sel[b * M_BLK + kb] || kb == qblk);
        wlive[i]   = (kb <= qbmax) && (sel[b * M_BLK + kb] || kb >= qbmin);
        float2 vv = make_float2(-1e9f, -1e9f);
        if (blive) vv = *reinterpret_cast<const float2*>(s + row + 2 * p);
        int e0 = 2 * p;
        v[2*i]   = (blive && e0     <= tq) ? vv.x * scale : -1e9f;
        v[2*i+1] = (blive && e0 + 1 <= tq) ? vv.y * scale : -1e9f;
        mx = fmaxf(mx, fmaxf(v[2*i], v[2*i+1]));
    }
    for (int o = 16; o > 0; o >>= 1) mx = fmaxf(mx, __shfl_xor_sync(0xffffffffu, mx, o));
    __shared__ float red[8];
    if ((tid & 31) == 0) red[tid >> 5] = mx;
    __syncthreads();
    float m = red[0];
    for (int i = 1; i < 8; i++) m = fmaxf(m, red[i]);
    __syncthreads();
    float sum = 0.f;
#pragma unroll
    for (int i = 0; i < 4; i++) { v[i] = expf(v[i] - m); sum += v[i]; }
    for (int o = 16; o > 0; o >>= 1) sum += __shfl_xor_sync(0xffffffffu, sum, o);
    if ((tid & 31) == 0) red[tid >> 5] = sum;
    __syncthreads();
    float tot = 0.f;
    for (int i = 0; i < 8; i++) tot += red[i];
    float inv = 1.f / tot;
    size_t prow = row >> 1;
#pragma unroll
    for (int i = 0; i < 2; i++) {
        if (!wlive[i]) continue;
        int p = tid + i * 256;
        u32 hh_, ll_;
        split2(v[2*i] * inv, v[2*i+1] * inv, hh_, ll_);
        ph[prow + p] = hh_; pl[prow + p] = ll_;
    }
}

// SiLU gate fused with split: f13 = [f1 | f3] contiguous
__global__ __launch_bounds__(256) void silu_split_kernel(const float* __restrict__ f13,
                                                         u32* __restrict__ gh, u32* __restrict__ gl,
                                                         long n2)
{
    long idx = (long)blockIdx.x * blockDim.x + threadIdx.x;
    if (idx >= n2) return;
    const long F3OFF = (long)B_SZ * T_SZ * FF_SZ / 2;
    float2 a = reinterpret_cast<const float2*>(f13)[idx];
    float2 g = reinterpret_cast<const float2*>(f13)[F3OFF + idx];
    float y0 = a.x / (1.f + expf(-a.x)) * g.x;
    float y1 = a.y / (1.f + expf(-a.y)) * g.y;
    u32 h, l;
    split2(y0, y1, h, l);
    gh[idx] = h; gl[idx] = l;
}

// ---------------- host launchers ----------------
static const int SMEM_KN64 = (2*128*LDA_S + 2*32*(64+8)) * 2 * 2;
static const int SMEM_NK64 = (2*128*LDA_S + 2*64*LDA_S)  * 2 * 2;

static void gemm_kn(const u16* Ah, const u16* Al, const u16* Bh, const u16* Bl, float* C,
                    int M, int N, int K, int lda, int ldb, int ldc,
                    long sAb, long sBb, long sCb, long sAh, long sBh, long sCh,
                    int Hdim, int nb, int beta,
                    const int* sel = 0, int smode = 0, u16* Ch = 0, u16* Cl = 0)
{
    dim3 grid(N / 64, M / 128, nb);
    bf16_gemm_kernel<false><<<grid, 256, SMEM_KN64>>>(
        Ah, Al, Bh, Bl, C, K, lda, ldb, ldc, sAb, sBb, sCb, sAh, sBh, sCh, Hdim, beta,
        sel, smode, (u32*)Ch, (u32*)Cl);
}

static void gemm_nk(const u16* Ah, const u16* Al, const u16* Bh, const u16* Bl, float* C,
                    int M, int N, int K, int lda, int ldb, int ldc,
                    long sAb, long sBb, long sCb, long sAh, long sBh, long sCh,
                    int Hdim, int nb, int beta, const int* sel, int smode)
{
    dim3 grid(N / 64, M / 128, nb);
    bf16_gemm_kernel<true><<<grid, 256, SMEM_NK64>>>(
        Ah, Al, Bh, Bl, C, K, lda, ldb, ldc, sAb, sBb, sCb, sAh, sBh, sCh, Hdim, beta,
        sel, smode, (u32*)0, (u32*)0);
}

static void split(const float* in, u16* hi, u16* lo, long n)
{
    long n4 = n / 4;
    split_kernel<<<(unsigned)((n4 + 255) / 256), 256>>>(in, (uint2*)hi, (uint2*)lo, n4);
}

extern "C" void kernel_launch(void* const* d_in, const int* in_sizes, int n_in,
                              void* d_out, int out_size)
{
    const int*   ids        = (const int*)  d_in[0];
    const float* emb        = (const float*)d_in[1];
    const float* wq         = (const float*)d_in[2];
    const float* wk         = (const float*)d_in[3];
    const float* wv         = (const float*)d_in[4];
    const float* wo         = (const float*)d_in[5];
    const float* w1         = (const float*)d_in[6];
    const float* w2         = (const float*)d_in[7];
    const float* w3         = (const float*)d_in[8];
    const float* attn_norm  = (const float*)d_in[9];
    const float* ffn_norm   = (const float*)d_in[10];
    const float* final_norm = (const float*)d_in[11];
    const float* lm_head    = (const float*)d_in[12];
    float* out = (float*)d_out;

    static bool attrs_set = false;
    if (!attrs_set) {
        cudaFuncSetAttribute(bf16_gemm_kernel<false>,
                             cudaFuncAttributeMaxDynamicSharedMemorySize, SMEM_KN64);
        cudaFuncSetAttribute(bf16_gemm_kernel<true>,
                             cudaFuncAttributeMaxDynamicSharedMemorySize, SMEM_NK64);
        attrs_set = true;
    }

    float *x, *h, *qkv, *o, *sc, *f13, *G, *gk, *rho;
    int* sel;
    cudaGetSymbolAddress((void**)&x,   d_x);
    cudaGetSymbolAddress((void**)&h,   d_h);
    cudaGetSymbolAddress((void**)&qkv, d_qkv);
    cudaGetSymbolAddress((void**)&o,   d_o);
    cudaGetSymbolAddress((void**)&sc,  d_sc);
    cudaGetSymbolAddress((void**)&f13, d_f13);
    cudaGetSymbolAddress((void**)&G,   d_G);
    cudaGetSymbolAddress((void**)&gk,  d_gk);
    cudaGetSymbolAddress((void**)&rho, d_rho);
    cudaGetSymbolAddress((void**)&sel, d_sel);

    u16 *xh,*xl,*Gh,*Gl,*hh,*hl,*qkvh,*qkvl,*sch,*scl,*oh,*ol,*f1h,*f1l;
    u16 *wqkvh,*wqkvl,*woh,*wol,*w13h,*w13l,*w2h,*w2l,*lmh,*lml;
    cudaGetSymbolAddress((void**)&xh, d_xh);     cudaGetSymbolAddress((void**)&xl, d_xl);
    cudaGetSymbolAddress((void**)&Gh, d_Gh);     cudaGetSymbolAddress((void**)&Gl, d_Gl);
    cudaGetSymbolAddress((void**)&hh, d_hh);     cudaGetSymbolAddress((void**)&hl, d_hl);
    cudaGetSymbolAddress((void**)&qkvh, d_qkvh); cudaGetSymbolAddress((void**)&qkvl, d_qkvl);
    cudaGetSymbolAddress((void**)&sch, d_sch);   cudaGetSymbolAddress((void**)&scl, d_scl);
    cudaGetSymbolAddress((void**)&oh, d_oh);     cudaGetSymbolAddress((void**)&ol, d_ol);
    cudaGetSymbolAddress((void**)&f1h, d_f1h);   cudaGetSymbolAddress((void**)&f1l, d_f1l);
    cudaGetSymbolAddress((void**)&wqkvh, d_wqkvh); cudaGetSymbolAddress((void**)&wqkvl, d_wqkvl);
    cudaGetSymbolAddress((void**)&woh, d_woh);   cudaGetSymbolAddress((void**)&wol, d_wol);
    cudaGetSymbolAddress((void**)&w13h, d_w13h); cudaGetSymbolAddress((void**)&w13l, d_w13l);
    cudaGetSymbolAddress((void**)&w2h, d_w2h);   cudaGetSymbolAddress((void**)&w2l, d_w2l);
    cudaGetSymbolAddress((void**)&lmh, d_lmh);   cudaGetSymbolAddress((void**)&lml, d_lml);

    const int  BT = B_SZ * T_SZ;
    const long DD = (long)D_SZ * D_SZ;
    const long DF = (long)D_SZ * FF_SZ;
    const long QK = (long)BT * D_SZ;        // size of one q/k/v section

    // weight splits into concatenated plane buffers
    for (int l = 0; l < L_SZ; l++) {
        split(wq + l * DD, wqkvh + (3 * l + 0) * DD, wqkvl + (3 * l + 0) * DD, DD);
        split(wk + l * DD, wqkvh + (3 * l + 1) * DD, wqkvl + (3 * l + 1) * DD, DD);
        split(wv + l * DD, wqkvh + (3 * l + 2) * DD, wqkvl + (3 * l + 2) * DD, DD);
        split(w1 + l * DF, w13h + (2 * l + 0) * DF, w13l + (2 * l + 0) * DF, DF);
        split(w3 + l * DF, w13h + (2 * l + 1) * DF, w13l + (2 * l + 1) * DF, DF);
    }
    split(wo, woh, wol, (long)L_SZ * DD);
    split(w2, w2h, w2l, (long)L_SZ * DF);
    split(lm_head, lmh, lml, (long)D_SZ * V_SZ);

    // 1) embedding (+split)
    embed_split_kernel<<<(B_SZ * T_SZ * D_SZ / 2) / 256, 256>>>(
        ids, emb, x, (u32*)xh, (u32*)xl);

    // 2) low-pass quality -> block selection
    dirichlet_kernel<<<T_SZ / 256, 256>>>(gk);
    buildG_kernel<<<(T_SZ * T_SZ) / 256, 256>>>(gk, G);
    split(G, Gh, Gl, (long)T_SZ * T_SZ);
    gemm_kn(Gh, Gl, xh, xl, h, T_SZ, D_SZ, T_SZ, T_SZ, D_SZ, D_SZ,
            0, (long)T_SZ * D_SZ, (long)T_SZ * D_SZ, 0, 0, 0, 1, B_SZ, 0);
    rho_kernel<<<BT, 256>>>(h, x, rho);
    select_blocks<<<1, 64>>>(rho, sel);

    // 3) transformer layers
    for (int l = 0; l < L_SZ; l++) {
        rmsnorm_split_kernel<<<BT, 256>>>(x, attn_norm + (size_t)l * D_SZ, (u32*)hh, (u32*)hl);

        // fused QKV: z in {0,1,2} selects weight segment + output section
        gemm_kn(hh, hl, wqkvh + 3 * l * DD, wqkvl + 3 * l * DD, qkv,
                BT, D_SZ, D_SZ, D_SZ, D_SZ, D_SZ,
                0, 0, 0, 0, DD, QK, 3, 3, 0, 0, 0,
                (u16*)qkvh, (u16*)qkvl);

        rope_split_kernel<<<(B_SZ * T_SZ * H_SZ * 16) / 256, 256>>>(
            qkv, (u32*)qkvh, (u32*)qkvl);

        // scores[b,h] = q_head @ k_head^T (sparse output tiles)
        gemm_nk(qkvh, qkvl, qkvh + QK, qkvl + QK, sc, T_SZ, T_SZ, DH_SZ,
                D_SZ, D_SZ, T_SZ,
                (long)T_SZ * D_SZ, (long)T_SZ * D_SZ, (long)H_SZ * T_SZ * T_SZ,
                DH_SZ, DH_SZ, (long)T_SZ * T_SZ, H_SZ, B_SZ * H_SZ, 0, sel, 1);

        masked_softmax_split_kernel<<<B_SZ * H_SZ * T_SZ, 256>>>(
            sc, sel, (u32*)sch, (u32*)scl);

        // o_head = attn @ v_head (sparse K blocks; emits o planes)
        gemm_kn(sch, scl, qkvh + 2 * QK, qkvl + 2 * QK, o, T_SZ, DH_SZ, T_SZ,
                T_SZ, D_SZ, D_SZ,
                (long)H_SZ * T_SZ * T_SZ, (long)T_SZ * D_SZ, (long)T_SZ * D_SZ,
                (long)T_SZ * T_SZ, DH_SZ, DH_SZ, H_SZ, B_SZ * H_SZ, 0, sel, 2, oh, ol);

        gemm_kn(oh, ol, woh + l * DD, wol + l * DD, x, BT, D_SZ, D_SZ, D_SZ, D_SZ, D_SZ,
                0, 0, 0, 0, 0, 0, 1, 1, 1);

        // FFN: fused w1/w3 (z in {0,1})
        rmsnorm_split_kernel<<<BT, 256>>>(x, ffn_norm + (size_t)l * D_SZ, (u32*)hh, (u32*)hl);
        gemm_kn(hh, hl, w13h + 2 * l * DF, w13l + 2 * l * DF, f13,
                BT, FF_SZ, D_SZ, D_SZ, FF_SZ, FF_SZ,
                0, 0, 0, 0, DF, (long)BT * FF_SZ, 2, 2, 0);
        silu_split_kernel<<<(BT * FF_SZ / 2 + 255) / 256, 256>>>(
            f13, (u32*)f1h, (u32*)f1l, (long)BT * FF_SZ / 2);
        gemm_kn(f1h, f1l, w2h + l * DF, w2l + l * DF, x, BT, D_SZ, FF_SZ, FF_SZ, D_SZ, D_SZ,
                0, 0, 0, 0, 0, 0, 1, 1, 1);
    }

    // 4) final norm + lm_head
    rmsnorm_split_kernel<<<BT, 256>>>(x, final_norm, (u32*)hh, (u32*)hl);
    gemm_kn(hh, hl, lmh, lml, out, BT, V_SZ, D_SZ, D_SZ, V_SZ, V_SZ,
            0, 0, 0, 0, 0, 0, 1, 1, 0);
}